// round 1
// baseline (speedup 1.0000x reference)
#include <cuda_runtime.h>
#include <math.h>

#define N_  2048
#define D_  1024
#define U_  2048
#define NB_ 4
#define M_  8192
#define MD_ 1024

// ---------------- scratch (device globals: no allocs allowed) ----------------
__device__ float g_wc[D_ * U_ * NB_];   // [D, U*NB] = [1024, 8192]  w * sigmoid(delay)
__device__ float g_gate[N_ * NB_];      // [N, 4] softmaxed gate
__device__ float g_cm[U_];              // conn[u] * mask[u]
__device__ float g_wts[8];              // softmax(act_w)[0..7]
__device__ float g_blend[N_ * U_];      // [2048, 2048]
__device__ float g_attn[N_ * M_];       // [2048, 8192] logits -> attn (in place)

// ---------------- helpers ----------------
__device__ __forceinline__ void ffma2(unsigned long long& d, unsigned long long a,
                                      unsigned long long b) {
    // packed f32x2 FMA: d.lo = a.lo*b.lo + d.lo ; d.hi = a.hi*b.hi + d.hi
    asm("fma.rn.f32x2 %0, %1, %2, %0;" : "+l"(d) : "l"(a), "l"(b));
}
__device__ __forceinline__ float2 up(unsigned long long v) {
    float2 r;
    asm("mov.b64 {%0, %1}, %2;" : "=f"(r.x), "=f"(r.y) : "l"(v));
    return r;
}
__device__ __forceinline__ float sigmoidf_(float x) { return 1.f / (1.f + expf(-x)); }

// ---------------- small prep kernels ----------------
__global__ void k_prep_wc(const float4* __restrict__ w, const float4* __restrict__ delay) {
    int i = blockIdx.x * blockDim.x + threadIdx.x;   // 2,097,152 float4s
    float4 wv = w[i], dv = delay[i];
    float4 o;
    o.x = wv.x * sigmoidf_(dv.x);
    o.y = wv.y * sigmoidf_(dv.y);
    o.z = wv.z * sigmoidf_(dv.z);
    o.w = wv.w * sigmoidf_(dv.w);
    reinterpret_cast<float4*>(g_wc)[i] = o;
}

__global__ void k_gate(const float* __restrict__ x, const float* __restrict__ gW,
                       const float* __restrict__ gb) {
    int n = blockIdx.x;
    int t = threadIdx.x;  // 128 threads
    float4 s = make_float4(0.f, 0.f, 0.f, 0.f);
    for (int d = t; d < D_; d += 128) {
        float xv = x[n * D_ + d];
        float4 g = *(const float4*)&gW[d * 4];
        s.x += xv * g.x; s.y += xv * g.y; s.z += xv * g.z; s.w += xv * g.w;
    }
    __shared__ float4 sh[128];
    sh[t] = s;
    __syncthreads();
    for (int o = 64; o > 0; o >>= 1) {
        if (t < o) {
            sh[t].x += sh[t + o].x; sh[t].y += sh[t + o].y;
            sh[t].z += sh[t + o].z; sh[t].w += sh[t + o].w;
        }
        __syncthreads();
    }
    if (t == 0) {
        float4 v = sh[0];
        float l0 = v.x + gb[0], l1 = v.y + gb[1], l2 = v.z + gb[2], l3 = v.w + gb[3];
        float mx = fmaxf(fmaxf(l0, l1), fmaxf(l2, l3));
        float e0 = expf(l0 - mx), e1 = expf(l1 - mx), e2 = expf(l2 - mx), e3 = expf(l3 - mx);
        float inv = 1.f / (e0 + e1 + e2 + e3);
        *(float4*)&g_gate[n * 4] = make_float4(e0 * inv, e1 * inv, e2 * inv, e3 * inv);
    }
}

__global__ void k_conn(const float* __restrict__ na, const float* __restrict__ W1,
                       const float* __restrict__ b1, const float* __restrict__ W2,
                       const float* __restrict__ b2, const float* __restrict__ mask) {
    __shared__ float h[32];
    __shared__ float red[256];
    int t = threadIdx.x;      // 256 threads
    int j = t >> 3, l = t & 7;
    float p = 0.f;
    for (int u = l; u < U_; u += 8) p += na[u] * W1[u * 32 + j];
    red[t] = p;
    __syncthreads();
    if (l == 0) {
        float s = 0.f;
        for (int q = 0; q < 8; q++) s += red[j * 8 + q];
        h[j] = fmaxf(s + b1[j], 0.f);
    }
    __syncthreads();
    for (int u = t; u < U_; u += 256) {
        float s = b2[u];
        #pragma unroll
        for (int jj = 0; jj < 32; jj++) s += h[jj] * W2[jj * U_ + u];
        g_cm[u] = mask[u] * sigmoidf_(s);
    }
}

__global__ void k_actw(const float* __restrict__ aw) {
    if (threadIdx.x == 0) {
        float m = -1e30f;
        for (int i = 0; i < 9; i++) m = fmaxf(m, aw[i]);
        float e[9], s = 0.f;
        for (int i = 0; i < 9; i++) { e[i] = expf(aw[i] - m); s += e[i]; }
        float inv = 1.f / s;
        for (int i = 0; i < 8; i++) g_wts[i] = e[i] * inv;
    }
}

// ---------------- SGEMM core (128x128 tile, BK=16, 8x8/thread, FFMA2) ----------------
// A [M,K] row-major, B [K,N] row-major. 256 threads. Grid: (N/128, M/128).
// A stored duplicated in smem so LDS yields packed f32x2 broadcast pairs.
__device__ __forceinline__ void gemm_core(const float* __restrict__ A,
                                          const float* __restrict__ B,
                                          int K, int N,
                                          unsigned long long (&acc2)[8][4]) {
    __shared__ __align__(16) float As2[16][256];
    __shared__ __align__(16) float Bs[16][128];
    const int tid = threadIdx.x;
    const int tx = tid & 15, ty = tid >> 4;
    const int rowBase = blockIdx.y * 128;
    const int colBase = blockIdx.x * 128;

    #pragma unroll
    for (int i = 0; i < 8; i++)
        #pragma unroll
        for (int jp = 0; jp < 4; jp++) acc2[i][jp] = 0ULL;

    const float* Aptr = A + (size_t)rowBase * K;

    for (int k0 = 0; k0 < K; k0 += 16) {
        // A tile: 128 rows x 16 cols -> As2[k][2m] duplicated
        #pragma unroll
        for (int i = 0; i < 2; i++) {
            int l4 = tid + i * 256;
            int c4 = l4 & 3, r = l4 >> 2;
            float4 v = *(const float4*)&Aptr[(size_t)r * K + k0 + c4 * 4];
            int kk = c4 * 4;
            *(float2*)&As2[kk + 0][2 * r] = make_float2(v.x, v.x);
            *(float2*)&As2[kk + 1][2 * r] = make_float2(v.y, v.y);
            *(float2*)&As2[kk + 2][2 * r] = make_float2(v.z, v.z);
            *(float2*)&As2[kk + 3][2 * r] = make_float2(v.w, v.w);
        }
        // B tile: 16 rows x 128 cols
        #pragma unroll
        for (int i = 0; i < 2; i++) {
            int l4 = tid + i * 256;
            int c4 = l4 & 31, r = l4 >> 5;
            *(float4*)&Bs[r][c4 * 4] = *(const float4*)&B[(size_t)(k0 + r) * N + colBase + c4 * 4];
        }
        __syncthreads();
        #pragma unroll
        for (int k = 0; k < 16; k++) {
            ulonglong2 qa0 = *(const ulonglong2*)&As2[k][ty * 8];
            ulonglong2 qa1 = *(const ulonglong2*)&As2[k][ty * 8 + 4];
            ulonglong2 qa2 = *(const ulonglong2*)&As2[k][ty * 8 + 128];
            ulonglong2 qa3 = *(const ulonglong2*)&As2[k][ty * 8 + 132];
            ulonglong2 qb0 = *(const ulonglong2*)&Bs[k][tx * 4];
            ulonglong2 qb1 = *(const ulonglong2*)&Bs[k][tx * 4 + 64];
            unsigned long long ad[8] = {qa0.x, qa0.y, qa1.x, qa1.y,
                                        qa2.x, qa2.y, qa3.x, qa3.y};
            unsigned long long bp[4] = {qb0.x, qb0.y, qb1.x, qb1.y};
            #pragma unroll
            for (int i = 0; i < 8; i++)
                #pragma unroll
                for (int jp = 0; jp < 4; jp++)
                    ffma2(acc2[i][jp], ad[i], bp[jp]);
        }
        __syncthreads();
    }
}

// row index for accumulator slot i
__device__ __forceinline__ int acc_row(int rowBase, int ty, int i) {
    return rowBase + (i < 4 ? ty * 4 + i : 64 + ty * 4 + (i - 4));
}

// ---------------- GEMM1: x @ wc + b -> gate-contract -> conn/mask/relu -> act-blend ----------------
__device__ __forceinline__ float blendf(float a, const float* w) {
    // a >= 0 guaranteed (post-relu). elu(a)=a, relu(a)=a, selu(a)=scale*a on a>=0.
    const float SELU_SCALE = 1.0507009873554804934f;
    float sig  = 1.f / (1.f + expf(-a));
    float th   = tanhf(a);
    float gelu = 0.5f * a * (1.f + erff(a * 0.70710678118654752440f));
    float sp   = a + log1pf(expf(-a));      // softplus, stable for a>=0
    float mish = a * tanhf(sp);
    return w[0] * sig + w[2] * th + (w[1] + w[3] + SELU_SCALE * w[6]) * a
         + w[4] * a * sig + w[5] * gelu + w[7] * mish;
}

__global__ void __launch_bounds__(256, 2)
k_gemm1(const float* __restrict__ x, const float* __restrict__ bvec) {
    unsigned long long acc2[8][4];
    gemm_core(x, g_wc, D_, U_ * NB_, acc2);
    const int tid = threadIdx.x, tx = tid & 15, ty = tid >> 4;
    const int rowBase = blockIdx.y * 128, colBase = blockIdx.x * 128;
    const int c0 = colBase + tx * 4, c1 = c0 + 64;
    const int u0 = c0 >> 2, u1 = c1 >> 2;
    float4 b0 = *(const float4*)&bvec[c0];
    float4 b1 = *(const float4*)&bvec[c1];
    float cm0 = g_cm[u0], cm1 = g_cm[u1];
    float w[8];
    #pragma unroll
    for (int q = 0; q < 8; q++) w[q] = g_wts[q];
    #pragma unroll
    for (int i = 0; i < 8; i++) {
        int row = acc_row(rowBase, ty, i);
        float4 gg = *(const float4*)&g_gate[row * 4];
        float2 p0 = up(acc2[i][0]), p1 = up(acc2[i][1]);
        float2 p2 = up(acc2[i][2]), p3 = up(acc2[i][3]);
        float z0 = (p0.x + b0.x) * gg.x + (p0.y + b0.y) * gg.y
                 + (p1.x + b0.z) * gg.z + (p1.y + b0.w) * gg.w;
        float z1 = (p2.x + b1.x) * gg.x + (p2.y + b1.y) * gg.y
                 + (p3.x + b1.z) * gg.z + (p3.y + b1.w) * gg.w;
        g_blend[row * U_ + u0] = blendf(fmaxf(z0 * cm0, 0.f), w);
        g_blend[row * U_ + u1] = blendf(fmaxf(z1 * cm1, 0.f), w);
    }
}

// ---------------- GEMM2: blend @ read_W + read_b -> logits ----------------
__global__ void __launch_bounds__(256, 2)
k_gemm2(const float* __restrict__ rW, const float* __restrict__ rb) {
    unsigned long long acc2[8][4];
    gemm_core(g_blend, rW, U_, M_, acc2);
    const int tid = threadIdx.x, tx = tid & 15, ty = tid >> 4;
    const int rowBase = blockIdx.y * 128, colBase = blockIdx.x * 128;
    const int c0 = colBase + tx * 4, c1 = c0 + 64;
    float4 rb0 = *(const float4*)&rb[c0];
    float4 rb1 = *(const float4*)&rb[c1];
    #pragma unroll
    for (int i = 0; i < 8; i++) {
        int row = acc_row(rowBase, ty, i);
        float2 p0 = up(acc2[i][0]), p1 = up(acc2[i][1]);
        float2 p2 = up(acc2[i][2]), p3 = up(acc2[i][3]);
        float4 o0 = make_float4(p0.x + rb0.x, p0.y + rb0.y, p1.x + rb0.z, p1.y + rb0.w);
        float4 o1 = make_float4(p2.x + rb1.x, p2.y + rb1.y, p3.x + rb1.z, p3.y + rb1.w);
        *(float4*)&g_attn[(size_t)row * M_ + c0] = o0;
        *(float4*)&g_attn[(size_t)row * M_ + c1] = o1;
    }
}

// ---------------- softmax over M=8192 per row (row held in registers) ----------------
__global__ void __launch_bounds__(256) k_softmax() {
    __shared__ float sm[256];
    int n = blockIdx.x, t = threadIdx.x;
    float4* row4 = (float4*)&g_attn[(size_t)n * M_];
    float4 v[8];
    float mx = -3.4e38f;
    #pragma unroll
    for (int i = 0; i < 8; i++) {
        v[i] = row4[t + i * 256];
        mx = fmaxf(mx, fmaxf(fmaxf(v[i].x, v[i].y), fmaxf(v[i].z, v[i].w)));
    }
    sm[t] = mx; __syncthreads();
    for (int o = 128; o > 0; o >>= 1) {
        if (t < o) sm[t] = fmaxf(sm[t], sm[t + o]);
        __syncthreads();
    }
    mx = sm[0];
    __syncthreads();
    float s = 0.f;
    #pragma unroll
    for (int i = 0; i < 8; i++) {
        v[i].x = expf(v[i].x - mx); v[i].y = expf(v[i].y - mx);
        v[i].z = expf(v[i].z - mx); v[i].w = expf(v[i].w - mx);
        s += v[i].x + v[i].y + v[i].z + v[i].w;
    }
    sm[t] = s; __syncthreads();
    for (int o = 128; o > 0; o >>= 1) {
        if (t < o) sm[t] += sm[t + o];
        __syncthreads();
    }
    float inv = 1.f / sm[0];
    #pragma unroll
    for (int i = 0; i < 8; i++) {
        v[i].x *= inv; v[i].y *= inv; v[i].z *= inv; v[i].w *= inv;
        row4[t + i * 256] = v[i];
    }
}

// ---------------- GEMM3: attn @ memory -> out ----------------
__global__ void __launch_bounds__(256, 2)
k_gemm3(const float* __restrict__ mem, float* __restrict__ out) {
    unsigned long long acc2[8][4];
    gemm_core(g_attn, mem, M_, MD_, acc2);
    const int tid = threadIdx.x, tx = tid & 15, ty = tid >> 4;
    const int rowBase = blockIdx.y * 128, colBase = blockIdx.x * 128;
    const int c0 = colBase + tx * 4, c1 = c0 + 64;
    #pragma unroll
    for (int i = 0; i < 8; i++) {
        int row = acc_row(rowBase, ty, i);
        float2 p0 = up(acc2[i][0]), p1 = up(acc2[i][1]);
        float2 p2 = up(acc2[i][2]), p3 = up(acc2[i][3]);
        *(float4*)&out[(size_t)row * MD_ + c0] = make_float4(p0.x, p0.y, p1.x, p1.y);
        *(float4*)&out[(size_t)row * MD_ + c1] = make_float4(p2.x, p2.y, p3.x, p3.y);
    }
}

// ---------------- launch ----------------
extern "C" void kernel_launch(void* const* d_in, const int* in_sizes, int n_in,
                              void* d_out, int out_size) {
    const float* x        = (const float*)d_in[0];
    const float* w        = (const float*)d_in[1];
    const float* delay    = (const float*)d_in[2];
    const float* b        = (const float*)d_in[3];
    const float* gate_W   = (const float*)d_in[4];
    const float* gate_b   = (const float*)d_in[5];
    const float* navg     = (const float*)d_in[6];
    const float* conn_W1  = (const float*)d_in[7];
    const float* conn_b1  = (const float*)d_in[8];
    const float* conn_W2  = (const float*)d_in[9];
    const float* conn_b2  = (const float*)d_in[10];
    const float* mask     = (const float*)d_in[11];
    const float* act_w    = (const float*)d_in[12];
    const float* read_W   = (const float*)d_in[13];
    const float* read_b   = (const float*)d_in[14];
    const float* memory   = (const float*)d_in[15];
    float* out = (float*)d_out;

    k_prep_wc<<<(D_ * U_ * NB_ / 4) / 256, 256>>>((const float4*)w, (const float4*)delay);
    k_gate<<<N_, 128>>>(x, gate_W, gate_b);
    k_conn<<<1, 256>>>(navg, conn_W1, conn_b1, conn_W2, conn_b2, mask);
    k_actw<<<1, 32>>>(act_w);
    k_gemm1<<<dim3(U_ * NB_ / 128, N_ / 128), 256>>>(x, b);
    k_gemm2<<<dim3(M_ / 128, N_ / 128), 256>>>(read_W, read_b);
    k_softmax<<<N_, 256>>>();
    k_gemm3<<<dim3(MD_ / 128, N_ / 128), 256>>>(memory, out);
}

// round 3
// speedup vs baseline: 3.0527x; 3.0527x over previous
#include <cuda_runtime.h>
#include <math.h>
#include <stdint.h>

#define N_  2048
#define D_  1024
#define U_  2048
#define NB_ 4
#define M_  8192
#define MD_ 1024

// ---------------- scratch (device globals; no allocs allowed) ----------------
__device__ __align__(16) float g_wct[(size_t)U_ * NB_ * D_];   // (w*sig(delay))^T [8192,1024]
__device__ __align__(16) float g_rwt[(size_t)M_ * U_];         // read_W^T [8192,2048]
__device__ __align__(16) float g_memt[(size_t)MD_ * M_];       // memory^T [1024,8192]
__device__ __align__(16) float g_blend[(size_t)N_ * U_];       // [2048,2048]
__device__ __align__(16) float g_logits[(size_t)N_ * M_];      // [2048,8192]
__device__ __align__(16) float g_attnd[(size_t)N_ * M_];       // attn - 1/M
__device__ float g_colmean[MD_];
__device__ float g_gate[N_ * NB_];
__device__ float g_cm[U_];
__device__ float g_wts[8];

// ---------------- PTX helpers ----------------
__device__ __forceinline__ uint32_t smem_u32(const void* p) {
    uint32_t a;
    asm("{ .reg .u64 t; cvta.to.shared.u64 t, %1; cvt.u32.u64 %0, t; }" : "=r"(a) : "l"(p));
    return a;
}
__device__ __forceinline__ void cp16(uint32_t s, const void* g) {
    asm volatile("cp.async.cg.shared.global [%0], [%1], 16;" :: "r"(s), "l"(g));
}
__device__ __forceinline__ void cp_commit() { asm volatile("cp.async.commit_group;"); }
template<int NN> __device__ __forceinline__ void cp_wait() {
    asm volatile("cp.async.wait_group %0;" :: "n"(NN));
}
__device__ __forceinline__ float lds_f(uint32_t a) {
    float v;
    asm("ld.shared.f32 %0, [%1];" : "=f"(v) : "r"(a));
    return v;
}
__device__ __forceinline__ uint32_t to_tf32(float f) {
    uint32_t o;
    asm("cvt.rna.tf32.f32 %0, %1;" : "=r"(o) : "f"(f));
    return o;
}
__device__ __forceinline__ void mma_tf32(float* c, const uint32_t* a, const uint32_t* b) {
    asm volatile(
        "mma.sync.aligned.m16n8k8.row.col.f32.tf32.tf32.f32 "
        "{%0,%1,%2,%3}, {%4,%5,%6,%7}, {%8,%9}, {%0,%1,%2,%3};"
        : "+f"(c[0]), "+f"(c[1]), "+f"(c[2]), "+f"(c[3])
        : "r"(a[0]), "r"(a[1]), "r"(a[2]), "r"(a[3]), "r"(b[0]), "r"(b[1]));
}
__device__ __forceinline__ uint32_t swz(uint32_t b) { return b ^ ((b >> 3) & 0x70); }
__device__ __forceinline__ float sigmoidf_(float x) { return 1.f / (1.f + expf(-x)); }
__device__ __forceinline__ float tanh_ap(float x) {
    float r;
    asm("tanh.approx.f32 %0, %1;" : "=f"(r) : "f"(x));
    return r;
}

// ---------------- prep kernels ----------------
__global__ void k_prep_wct(const float* __restrict__ w, const float* __restrict__ delay) {
    __shared__ float t[32][33];
    int j0 = blockIdx.x * 32, d0 = blockIdx.y * 32;
    int tx = threadIdx.x, ty = threadIdx.y;
    #pragma unroll
    for (int i = 0; i < 4; i++) {
        size_t idx = (size_t)(d0 + ty + i * 8) * (U_ * NB_) + j0 + tx;
        t[ty + i * 8][tx] = w[idx] * sigmoidf_(delay[idx]);
    }
    __syncthreads();
    #pragma unroll
    for (int i = 0; i < 4; i++)
        g_wct[(size_t)(j0 + ty + i * 8) * D_ + d0 + tx] = t[tx][ty + i * 8];
}

__global__ void k_transpose(const float* __restrict__ src, float* __restrict__ dst,
                            int R, int C) {
    __shared__ float t[32][33];
    int c0 = blockIdx.x * 32, r0 = blockIdx.y * 32;
    int tx = threadIdx.x, ty = threadIdx.y;
    #pragma unroll
    for (int i = 0; i < 4; i++)
        t[ty + i * 8][tx] = src[(size_t)(r0 + ty + i * 8) * C + c0 + tx];
    __syncthreads();
    #pragma unroll
    for (int i = 0; i < 4; i++)
        dst[(size_t)(c0 + ty + i * 8) * R + r0 + tx] = t[tx][ty + i * 8];
}

__global__ void k_colmean(const float* __restrict__ mem) {
    __shared__ float red[8][32];
    int j = blockIdx.x * 32 + threadIdx.x;
    int ty = threadIdx.y;
    float s = 0.f;
    for (int i = ty; i < M_; i += 8) s += mem[(size_t)i * MD_ + j];
    red[ty][threadIdx.x] = s;
    __syncthreads();
    if (ty == 0) {
        float tot = 0.f;
        #pragma unroll
        for (int q = 0; q < 8; q++) tot += red[q][threadIdx.x];
        g_colmean[j] = tot * (1.f / (float)M_);
    }
}

__global__ void k_gate(const float* __restrict__ x, const float* __restrict__ gW,
                       const float* __restrict__ gb) {
    int n = blockIdx.x;
    int t = threadIdx.x;  // 128 threads
    float4 s = make_float4(0.f, 0.f, 0.f, 0.f);
    for (int d = t; d < D_; d += 128) {
        float xv = x[n * D_ + d];
        float4 g = *(const float4*)&gW[d * 4];
        s.x += xv * g.x; s.y += xv * g.y; s.z += xv * g.z; s.w += xv * g.w;
    }
    __shared__ float4 sh[128];
    sh[t] = s;
    __syncthreads();
    for (int o = 64; o > 0; o >>= 1) {
        if (t < o) {
            sh[t].x += sh[t + o].x; sh[t].y += sh[t + o].y;
            sh[t].z += sh[t + o].z; sh[t].w += sh[t + o].w;
        }
        __syncthreads();
    }
    if (t == 0) {
        float4 v = sh[0];
        float l0 = v.x + gb[0], l1 = v.y + gb[1], l2 = v.z + gb[2], l3 = v.w + gb[3];
        float mx = fmaxf(fmaxf(l0, l1), fmaxf(l2, l3));
        float e0 = expf(l0 - mx), e1 = expf(l1 - mx), e2 = expf(l2 - mx), e3 = expf(l3 - mx);
        float inv = 1.f / (e0 + e1 + e2 + e3);
        *(float4*)&g_gate[n * 4] = make_float4(e0 * inv, e1 * inv, e2 * inv, e3 * inv);
    }
}

__global__ void k_conn(const float* __restrict__ na, const float* __restrict__ W1,
                       const float* __restrict__ b1, const float* __restrict__ W2,
                       const float* __restrict__ b2, const float* __restrict__ mask) {
    __shared__ float h[32];
    __shared__ float red[256];
    int t = threadIdx.x;
    int j = t >> 3, l = t & 7;
    float p = 0.f;
    for (int u = l; u < U_; u += 8) p += na[u] * W1[u * 32 + j];
    red[t] = p;
    __syncthreads();
    if (l == 0) {
        float s = 0.f;
        for (int q = 0; q < 8; q++) s += red[j * 8 + q];
        h[j] = fmaxf(s + b1[j], 0.f);
    }
    __syncthreads();
    for (int u = t; u < U_; u += 256) {
        float s = b2[u];
        #pragma unroll
        for (int jj = 0; jj < 32; jj++) s += h[jj] * W2[jj * U_ + u];
        g_cm[u] = mask[u] * sigmoidf_(s);
    }
}

__global__ void k_actw(const float* __restrict__ aw) {
    if (threadIdx.x == 0) {
        float m = -1e30f;
        for (int i = 0; i < 9; i++) m = fmaxf(m, aw[i]);
        float e[9], s = 0.f;
        for (int i = 0; i < 9; i++) { e[i] = expf(aw[i] - m); s += e[i]; }
        float inv = 1.f / s;
        for (int i = 0; i < 8; i++) g_wts[i] = e[i] * inv;
    }
}

// ---------------- activation blend (a >= 0 guaranteed) ----------------
__device__ __forceinline__ float blendf(float a, const float* w) {
    const float SELU_SCALE = 1.0507009873554804934f;
    float e = __expf(-a);
    float sig = __fdividef(1.f, 1.f + e);
    float th = tanh_ap(a);
    float gelu = 0.5f * a * (1.f + erff(a * 0.70710678118654752440f));
    float sp = a + __logf(1.f + e);           // softplus, stable for a>=0
    float mish = a * tanh_ap(sp);
    return w[0] * sig + w[2] * th + (w[1] + w[3] + SELU_SCALE * w[6]) * a
         + w[4] * a * sig + w[5] * gelu + w[7] * mish;
}

// ---------------- tf32 mma.sync GEMM: 128x128 tile, BK=32, 3-stage cp.async -------
// A [2048,K] fp32 row-major; Bt [Ncols,K] fp32 row-major (pre-transposed weights).
// 256 threads = 8 warps; warp tile 32(M) x 64(N); m16n8k8 tf32 fragments.
#define GSM_STAGE 16384
#define GSM_BOFF  49152
#define GSM_TOT   98304

template<int K, int EPI, int NDIM>
__global__ void __launch_bounds__(256, 2)
gemm_mma(const float* __restrict__ A, const float* __restrict__ Bt,
         const float* __restrict__ bias, float* __restrict__ outp) {
    extern __shared__ char smem[];
    const uint32_t sb = smem_u32(smem);
    const int tid = threadIdx.x;
    const int lane = tid & 31, wid = tid >> 5;
    const int wm = wid & 3, wn = wid >> 2;
    const int lrow = lane >> 2, lcol = lane & 3;
    const int m0 = blockIdx.y * 128, n0 = blockIdx.x * 128;
    constexpr int NC = K / 32;

    float acc[2][8][4];
    #pragma unroll
    for (int i = 0; i < 2; i++)
        #pragma unroll
        for (int j = 0; j < 8; j++)
            #pragma unroll
            for (int q = 0; q < 4; q++) acc[i][j][q] = 0.f;

    const float* Ab = A + (size_t)m0 * K;
    const float* Bb = Bt + (size_t)n0 * K;

    auto load_stage = [&](int c, int buf) {
        int k0 = c * 32;
        uint32_t sA = sb + buf * GSM_STAGE;
        uint32_t sB = sb + GSM_BOFF + buf * GSM_STAGE;
        #pragma unroll
        for (int i = 0; i < 4; i++) {
            int id = tid + i * 256;
            int r = id >> 3, cc = id & 7;
            cp16(sA + swz(r * 128 + cc * 16), Ab + (size_t)r * K + k0 + cc * 4);
        }
        #pragma unroll
        for (int i = 0; i < 4; i++) {
            int id = tid + i * 256;
            int r = id >> 3, cc = id & 7;
            cp16(sB + swz(r * 128 + cc * 16), Bb + (size_t)r * K + k0 + cc * 4);
        }
        cp_commit();
    };

    load_stage(0, 0);
    load_stage(1, 1);

    #pragma unroll 1
    for (int c = 0; c < NC; c++) {
        if (c + 1 < NC) cp_wait<1>(); else cp_wait<0>();
        __syncthreads();
        int buf = c % 3;
        uint32_t sA = sb + buf * GSM_STAGE;
        uint32_t sB = sb + GSM_BOFF + buf * GSM_STAGE;
        #pragma unroll
        for (int kk = 0; kk < 4; kk++) {
            uint32_t a[2][4], bf[8][2];
            #pragma unroll
            for (int i = 0; i < 2; i++) {
                int r = wm * 32 + i * 16 + lrow;
                int w = kk * 8 + lcol;
                a[i][0] = to_tf32(lds_f(sA + swz(r * 128 + w * 4)));
                a[i][1] = to_tf32(lds_f(sA + swz((r + 8) * 128 + w * 4)));
                a[i][2] = to_tf32(lds_f(sA + swz(r * 128 + (w + 4) * 4)));
                a[i][3] = to_tf32(lds_f(sA + swz((r + 8) * 128 + (w + 4) * 4)));
            }
            #pragma unroll
            for (int j = 0; j < 8; j++) {
                int n = wn * 64 + j * 8 + lrow;
                int w = kk * 8 + lcol;
                bf[j][0] = to_tf32(lds_f(sB + swz(n * 128 + w * 4)));
                bf[j][1] = to_tf32(lds_f(sB + swz(n * 128 + (w + 4) * 4)));
            }
            #pragma unroll
            for (int i = 0; i < 2; i++)
                #pragma unroll
                for (int j = 0; j < 8; j++)
                    mma_tf32(acc[i][j], a[i], bf[j]);
        }
        __syncthreads();
        if (c + 2 < NC) load_stage(c + 2, (c + 2) % 3);
    }

    // ---------------- epilogues ----------------
    if (EPI == 0) {
        // z = (branch + b) contracted with gate; a = relu(z*conn*mask); blend -> g_blend
        float w[8];
        #pragma unroll
        for (int q = 0; q < 8; q++) w[q] = g_wts[q];
        const int cb = (lane & 1) * 2;                  // gate component pair
        #pragma unroll
        for (int i = 0; i < 2; i++) {
            int r0 = m0 + wm * 32 + i * 16 + lrow;
            int r1 = r0 + 8;
            float gA0 = g_gate[r0 * 4 + cb], gA1 = g_gate[r0 * 4 + cb + 1];
            float gB0 = g_gate[r1 * 4 + cb], gB1 = g_gate[r1 * 4 + cb + 1];
            #pragma unroll
            for (int j = 0; j < 8; j++) {
                int col0 = n0 + wn * 64 + j * 8 + 2 * lcol;
                float bb0 = bias[col0], bb1 = bias[col0 + 1];
                float pl = (acc[i][j][0] + bb0) * gA0 + (acc[i][j][1] + bb1) * gA1;
                float ph = (acc[i][j][2] + bb0) * gB0 + (acc[i][j][3] + bb1) * gB1;
                pl += __shfl_xor_sync(0xFFFFFFFFu, pl, 1);
                ph += __shfl_xor_sync(0xFFFFFFFFu, ph, 1);
                float z = (lane & 1) ? ph : pl;
                int row = (lane & 1) ? r1 : r0;
                int u = (n0 + wn * 64 + j * 8 + (lane & 2) * 2) >> 2;
                float a = fmaxf(z * g_cm[u], 0.f);
                g_blend[(size_t)row * U_ + u] = blendf(a, w);
            }
        }
    } else if (EPI == 1) {
        #pragma unroll
        for (int i = 0; i < 2; i++) {
            int r0 = m0 + wm * 32 + i * 16 + lrow;
            int r1 = r0 + 8;
            #pragma unroll
            for (int j = 0; j < 8; j++) {
                int col0 = n0 + wn * 64 + j * 8 + 2 * lcol;
                float bb0 = bias[col0], bb1 = bias[col0 + 1];
                *(float2*)&g_logits[(size_t)r0 * NDIM + col0] =
                    make_float2(acc[i][j][0] + bb0, acc[i][j][1] + bb1);
                *(float2*)&g_logits[(size_t)r1 * NDIM + col0] =
                    make_float2(acc[i][j][2] + bb0, acc[i][j][3] + bb1);
            }
        }
    } else {
        #pragma unroll
        for (int i = 0; i < 2; i++) {
            int r0 = m0 + wm * 32 + i * 16 + lrow;
            int r1 = r0 + 8;
            #pragma unroll
            for (int j = 0; j < 8; j++) {
                int col0 = n0 + wn * 64 + j * 8 + 2 * lcol;
                float cm0 = g_colmean[col0], cm1 = g_colmean[col0 + 1];
                *(float2*)&outp[(size_t)r0 * NDIM + col0] =
                    make_float2(acc[i][j][0] + cm0, acc[i][j][1] + cm1);
                *(float2*)&outp[(size_t)r1 * NDIM + col0] =
                    make_float2(acc[i][j][2] + cm0, acc[i][j][3] + cm1);
            }
        }
    }
}

// ---------------- softmax: logits -> attn - 1/M (fp32) ----------------
__global__ void __launch_bounds__(256) k_softmax() {
    __shared__ float sm[256];
    int n = blockIdx.x, t = threadIdx.x;
    const float4* row4 = (const float4*)&g_logits[(size_t)n * M_];
    float4 v[8];
    float mx = -3.4e38f;
    #pragma unroll
    for (int i = 0; i < 8; i++) {
        v[i] = row4[t + i * 256];
        mx = fmaxf(mx, fmaxf(fmaxf(v[i].x, v[i].y), fmaxf(v[i].z, v[i].w)));
    }
    sm[t] = mx; __syncthreads();
    for (int o = 128; o > 0; o >>= 1) {
        if (t < o) sm[t] = fmaxf(sm[t], sm[t + o]);
        __syncthreads();
    }
    mx = sm[0]; __syncthreads();
    float s = 0.f;
    #pragma unroll
    for (int i = 0; i < 8; i++) {
        v[i].x = expf(v[i].x - mx); v[i].y = expf(v[i].y - mx);
        v[i].z = expf(v[i].z - mx); v[i].w = expf(v[i].w - mx);
        s += v[i].x + v[i].y + v[i].z + v[i].w;
    }
    sm[t] = s; __syncthreads();
    for (int o = 128; o > 0; o >>= 1) {
        if (t < o) sm[t] += sm[t + o];
        __syncthreads();
    }
    float inv = 1.f / sm[0];
    const float im = 1.f / (float)M_;
    float4* dst = (float4*)&g_attnd[(size_t)n * M_];
    #pragma unroll
    for (int i = 0; i < 8; i++) {
        dst[t + i * 256] = make_float4(v[i].x * inv - im, v[i].y * inv - im,
                                       v[i].z * inv - im, v[i].w * inv - im);
    }
}

// ---------------- launch ----------------
extern "C" void kernel_launch(void* const* d_in, const int* in_sizes, int n_in,
                              void* d_out, int out_size) {
    const float* x        = (const float*)d_in[0];
    const float* w        = (const float*)d_in[1];
    const float* delay    = (const float*)d_in[2];
    const float* b        = (const float*)d_in[3];
    const float* gate_W   = (const float*)d_in[4];
    const float* gate_b   = (const float*)d_in[5];
    const float* navg     = (const float*)d_in[6];
    const float* conn_W1  = (const float*)d_in[7];
    const float* conn_b1  = (const float*)d_in[8];
    const float* conn_W2  = (const float*)d_in[9];
    const float* conn_b2  = (const float*)d_in[10];
    const float* mask     = (const float*)d_in[11];
    const float* act_w    = (const float*)d_in[12];
    const float* read_W   = (const float*)d_in[13];
    const float* read_b   = (const float*)d_in[14];
    const float* memory   = (const float*)d_in[15];
    float* out = (float*)d_out;

    float* p_wct;   cudaGetSymbolAddress((void**)&p_wct, g_wct);
    float* p_rwt;   cudaGetSymbolAddress((void**)&p_rwt, g_rwt);
    float* p_memt;  cudaGetSymbolAddress((void**)&p_memt, g_memt);
    float* p_blend; cudaGetSymbolAddress((void**)&p_blend, g_blend);
    float* p_attnd; cudaGetSymbolAddress((void**)&p_attnd, g_attnd);

    cudaFuncSetAttribute(gemm_mma<D_, 0, U_ * NB_>,
                         cudaFuncAttributeMaxDynamicSharedMemorySize, GSM_TOT);
    cudaFuncSetAttribute(gemm_mma<U_, 1, M_>,
                         cudaFuncAttributeMaxDynamicSharedMemorySize, GSM_TOT);
    cudaFuncSetAttribute(gemm_mma<M_, 2, MD_>,
                         cudaFuncAttributeMaxDynamicSharedMemorySize, GSM_TOT);

    k_prep_wct<<<dim3(256, 32), dim3(32, 8)>>>(w, delay);
    k_transpose<<<dim3(256, 64), dim3(32, 8)>>>(read_W, p_rwt, U_, M_);
    k_transpose<<<dim3(32, 256), dim3(32, 8)>>>(memory, p_memt, M_, MD_);
    k_colmean<<<32, dim3(32, 8)>>>(memory);
    k_gate<<<N_, 128>>>(x, gate_W, gate_b);
    k_conn<<<1, 256>>>(navg, conn_W1, conn_b1, conn_W2, conn_b2, mask);
    k_actw<<<1, 32>>>(act_w);

    gemm_mma<D_, 0, U_ * NB_><<<dim3(64, 16), 256, GSM_TOT>>>(x, p_wct, b, nullptr);
    gemm_mma<U_, 1, M_><<<dim3(64, 16), 256, GSM_TOT>>>(p_blend, p_rwt, read_b, nullptr);
    k_softmax<<<N_, 256>>>();
    gemm_mma<M_, 2, MD_><<<dim3(8, 16), 256, GSM_TOT>>>(p_attnd, p_memt, nullptr, out);
}

// round 4
// speedup vs baseline: 5.4055x; 1.7707x over previous
#include <cuda_runtime.h>
#include <cuda_bf16.h>
#include <math.h>
#include <stdint.h>

#define N_  2048
#define D_  1024
#define U_  2048
#define NB_ 4
#define M_  8192
#define MD_ 1024

// ---------------- scratch (device globals; no allocs allowed) ----------------
__device__ __align__(16) __nv_bfloat16 g_xbf[(size_t)N_ * D_];        // x bf16 [2048,1024]
__device__ __align__(16) __nv_bfloat16 g_wct[(size_t)U_ * NB_ * D_];  // (w*sig)^T bf16 [8192,1024]
__device__ __align__(16) __nv_bfloat16 g_rwt[(size_t)M_ * U_];        // read_W^T bf16 [8192,2048]
__device__ __align__(16) __nv_bfloat16 g_blend[(size_t)N_ * U_];      // bf16 [2048,2048]
__device__ __align__(16) float g_memt[(size_t)MD_ * M_];              // memory^T tf32-rounded
__device__ __align__(16) float g_logits[(size_t)N_ * M_];             // fp32 [2048,8192]
__device__ __align__(16) float g_attnd[(size_t)N_ * M_];              // (attn-1/M) tf32-rounded
__device__ float g_cmpart[8 * MD_];                                   // colsum partials
__device__ float g_gate[N_ * NB_];
__device__ float g_cm[U_];
__device__ float g_wts[8];

// ---------------- PTX helpers ----------------
__device__ __forceinline__ uint32_t smem_u32(const void* p) {
    uint32_t a;
    asm("{ .reg .u64 t; cvta.to.shared.u64 t, %1; cvt.u32.u64 %0, t; }" : "=r"(a) : "l"(p));
    return a;
}
__device__ __forceinline__ void cp16(uint32_t s, const void* g) {
    asm volatile("cp.async.cg.shared.global [%0], [%1], 16;" :: "r"(s), "l"(g));
}
__device__ __forceinline__ void cp_commit() { asm volatile("cp.async.commit_group;"); }
template<int NN> __device__ __forceinline__ void cp_wait() {
    asm volatile("cp.async.wait_group %0;" :: "n"(NN));
}
__device__ __forceinline__ float lds_f(uint32_t a) {
    float v;
    asm("ld.shared.f32 %0, [%1];" : "=f"(v) : "r"(a));
    return v;
}
__device__ __forceinline__ uint32_t lds_u(uint32_t a) {
    uint32_t v;
    asm("ld.shared.b32 %0, [%1];" : "=r"(v) : "r"(a));
    return v;
}
__device__ __forceinline__ void ldsm4(uint32_t& r0, uint32_t& r1, uint32_t& r2, uint32_t& r3,
                                      uint32_t a) {
    asm volatile("ldmatrix.sync.aligned.m8n8.x4.shared.b16 {%0,%1,%2,%3}, [%4];"
                 : "=r"(r0), "=r"(r1), "=r"(r2), "=r"(r3) : "r"(a));
}
__device__ __forceinline__ void mma_bf16(float* c, const uint32_t* a, const uint32_t* b) {
    asm volatile(
        "mma.sync.aligned.m16n8k16.row.col.f32.bf16.bf16.f32 "
        "{%0,%1,%2,%3}, {%4,%5,%6,%7}, {%8,%9}, {%0,%1,%2,%3};"
        : "+f"(c[0]), "+f"(c[1]), "+f"(c[2]), "+f"(c[3])
        : "r"(a[0]), "r"(a[1]), "r"(a[2]), "r"(a[3]), "r"(b[0]), "r"(b[1]));
}
__device__ __forceinline__ void mma_tf32(float* c, const uint32_t* a, const uint32_t* b) {
    asm volatile(
        "mma.sync.aligned.m16n8k8.row.col.f32.tf32.tf32.f32 "
        "{%0,%1,%2,%3}, {%4,%5,%6,%7}, {%8,%9}, {%0,%1,%2,%3};"
        : "+f"(c[0]), "+f"(c[1]), "+f"(c[2]), "+f"(c[3])
        : "r"(a[0]), "r"(a[1]), "r"(a[2]), "r"(a[3]), "r"(b[0]), "r"(b[1]));
}
__device__ __forceinline__ float rna_tf32(float f) {
    uint32_t o;
    asm("cvt.rna.tf32.f32 %0, %1;" : "=r"(o) : "f"(f));
    return __uint_as_float(o);
}
__device__ __forceinline__ uint32_t swz(uint32_t b) { return b ^ ((b >> 3) & 0x70); }
__device__ __forceinline__ float sigmoidf_(float x) { return 1.f / (1.f + expf(-x)); }
__device__ __forceinline__ float tanh_ap(float x) {
    float r;
    asm("tanh.approx.f32 %0, %1;" : "=f"(r) : "f"(x));
    return r;
}

// ---------------- k_misc: gate softmax + conn + act weights + colsum partials ----------
__global__ void __launch_bounds__(256) k_misc(
    const float* __restrict__ x, const float* __restrict__ gW, const float* __restrict__ gb,
    const float* __restrict__ na, const float* __restrict__ W1, const float* __restrict__ b1,
    const float* __restrict__ W2, const float* __restrict__ b2, const float* __restrict__ mask,
    const float* __restrict__ aw, const float* __restrict__ mem) {
    __shared__ float4 sh4[256];
    __shared__ float red[256];
    __shared__ float h32[32];
    int bid = blockIdx.x, t = threadIdx.x;
    if (bid < N_) {
        // gate row
        float4 s = make_float4(0.f, 0.f, 0.f, 0.f);
        #pragma unroll
        for (int i = 0; i < 4; i++) {
            int d = t + i * 256;
            float xv = x[bid * D_ + d];
            float4 g = *(const float4*)&gW[d * 4];
            s.x += xv * g.x; s.y += xv * g.y; s.z += xv * g.z; s.w += xv * g.w;
        }
        sh4[t] = s;
        __syncthreads();
        for (int o = 128; o > 0; o >>= 1) {
            if (t < o) {
                sh4[t].x += sh4[t + o].x; sh4[t].y += sh4[t + o].y;
                sh4[t].z += sh4[t + o].z; sh4[t].w += sh4[t + o].w;
            }
            __syncthreads();
        }
        if (t == 0) {
            float4 v = sh4[0];
            float l0 = v.x + gb[0], l1 = v.y + gb[1], l2 = v.z + gb[2], l3 = v.w + gb[3];
            float mx = fmaxf(fmaxf(l0, l1), fmaxf(l2, l3));
            float e0 = expf(l0 - mx), e1 = expf(l1 - mx), e2 = expf(l2 - mx), e3 = expf(l3 - mx);
            float inv = 1.f / (e0 + e1 + e2 + e3);
            *(float4*)&g_gate[bid * 4] = make_float4(e0 * inv, e1 * inv, e2 * inv, e3 * inv);
        }
    } else if (bid == N_) {
        // conn MLP
        int j = t >> 3, l = t & 7;
        float p = 0.f;
        for (int u = l; u < U_; u += 8) p += na[u] * W1[u * 32 + j];
        red[t] = p;
        __syncthreads();
        if (l == 0) {
            float s = 0.f;
            for (int q = 0; q < 8; q++) s += red[j * 8 + q];
            h32[j] = fmaxf(s + b1[j], 0.f);
        }
        __syncthreads();
        for (int u = t; u < U_; u += 256) {
            float s = b2[u];
            #pragma unroll
            for (int jj = 0; jj < 32; jj++) s += h32[jj] * W2[jj * U_ + u];
            g_cm[u] = mask[u] * sigmoidf_(s);
        }
    } else if (bid == N_ + 1) {
        if (t == 0) {
            float m = -1e30f;
            for (int i = 0; i < 9; i++) m = fmaxf(m, aw[i]);
            float e[9], s = 0.f;
            for (int i = 0; i < 9; i++) { e[i] = expf(aw[i] - m); s += e[i]; }
            float inv = 1.f / s;
            for (int i = 0; i < 8; i++) g_wts[i] = e[i] * inv;
        }
    } else {
        // column-sum partials of memory: 256 blocks, each 32 cols x 1024 rows
        int bc = bid - (N_ + 2);
        int rc = bc >> 5, cc = bc & 31;
        int c = cc * 32 + (t & 31), ty = t >> 5;
        float s = 0.f;
        const float* p = mem + (size_t)(rc * 1024 + ty) * MD_ + c;
        #pragma unroll 4
        for (int i = 0; i < 128; i++) s += p[(size_t)i * 8 * MD_];
        red[t] = s;
        __syncthreads();
        if (ty == 0) {
            float tot = 0.f;
            #pragma unroll
            for (int q = 0; q < 8; q++) tot += red[q * 32 + (t & 31)];
            g_cmpart[rc * MD_ + c] = tot;
        }
    }
}

// ---------------- x -> bf16 ----------------
__global__ void k_cvt_x(const float4* __restrict__ x) {
    int i = blockIdx.x * blockDim.x + threadIdx.x;   // 524288 float4s
    float4 v = x[i];
    __nv_bfloat162* o = (__nv_bfloat162*)g_xbf;
    o[i * 2 + 0] = __floats2bfloat162_rn(v.x, v.y);
    o[i * 2 + 1] = __floats2bfloat162_rn(v.z, v.w);
}

// ---------------- transpose preps (float4 reads, vectorized bf16/fp32 writes) ----------
// src [R, C] fp32, tile 32(r) x 128(c); dst[c, r] in [C, R].
__global__ void __launch_bounds__(256) k_prep_wct(const float* __restrict__ w,
                                                  const float* __restrict__ delay) {
    __shared__ float tbuf[32][129];
    const int C = U_ * NB_;
    int j0 = blockIdx.x * 128, d0 = blockIdx.y * 32;
    int tx = threadIdx.x & 31, ty = threadIdx.x >> 5;
    #pragma unroll
    for (int i = 0; i < 4; i++) {
        int r = ty + i * 8;
        size_t idx = (size_t)(d0 + r) * C + j0 + tx * 4;
        float4 wv = *(const float4*)&w[idx];
        float4 dv = *(const float4*)&delay[idx];
        tbuf[r][tx * 4 + 0] = wv.x * sigmoidf_(dv.x);
        tbuf[r][tx * 4 + 1] = wv.y * sigmoidf_(dv.y);
        tbuf[r][tx * 4 + 2] = wv.z * sigmoidf_(dv.z);
        tbuf[r][tx * 4 + 3] = wv.w * sigmoidf_(dv.w);
    }
    __syncthreads();
    int jl = threadIdx.x >> 1, dh = (threadIdx.x & 1) << 4;
    __align__(16) __nv_bfloat16 ob[16];
    #pragma unroll
    for (int q = 0; q < 16; q++) ob[q] = __float2bfloat16(tbuf[dh + q][jl]);
    uint4* dst = (uint4*)&g_wct[(size_t)(j0 + jl) * D_ + d0 + dh];
    dst[0] = ((uint4*)ob)[0];
    dst[1] = ((uint4*)ob)[1];
}

__global__ void __launch_bounds__(256) k_prep_rwt(const float* __restrict__ src) {
    __shared__ float tbuf[32][129];
    const int C = M_, R = U_;
    int j0 = blockIdx.x * 128, u0 = blockIdx.y * 32;
    int tx = threadIdx.x & 31, ty = threadIdx.x >> 5;
    #pragma unroll
    for (int i = 0; i < 4; i++) {
        int r = ty + i * 8;
        float4 v = *(const float4*)&src[(size_t)(u0 + r) * C + j0 + tx * 4];
        tbuf[r][tx * 4 + 0] = v.x; tbuf[r][tx * 4 + 1] = v.y;
        tbuf[r][tx * 4 + 2] = v.z; tbuf[r][tx * 4 + 3] = v.w;
    }
    __syncthreads();
    int jl = threadIdx.x >> 1, dh = (threadIdx.x & 1) << 4;
    __align__(16) __nv_bfloat16 ob[16];
    #pragma unroll
    for (int q = 0; q < 16; q++) ob[q] = __float2bfloat16(tbuf[dh + q][jl]);
    uint4* dst = (uint4*)&g_rwt[(size_t)(j0 + jl) * R + u0 + dh];
    dst[0] = ((uint4*)ob)[0];
    dst[1] = ((uint4*)ob)[1];
}

__global__ void __launch_bounds__(256) k_prep_memt(const float* __restrict__ src) {
    __shared__ float tbuf[32][129];
    const int C = MD_, R = M_;
    int md0 = blockIdx.x * 128, m0 = blockIdx.y * 32;
    int tx = threadIdx.x & 31, ty = threadIdx.x >> 5;
    #pragma unroll
    for (int i = 0; i < 4; i++) {
        int r = ty + i * 8;
        float4 v = *(const float4*)&src[(size_t)(m0 + r) * C + md0 + tx * 4];
        tbuf[r][tx * 4 + 0] = v.x; tbuf[r][tx * 4 + 1] = v.y;
        tbuf[r][tx * 4 + 2] = v.z; tbuf[r][tx * 4 + 3] = v.w;
    }
    __syncthreads();
    int jl = threadIdx.x >> 1, mh = (threadIdx.x & 1) << 4;
    __align__(16) float ob[16];
    #pragma unroll
    for (int q = 0; q < 16; q++) ob[q] = rna_tf32(tbuf[mh + q][jl]);
    float4* dst = (float4*)&g_memt[(size_t)(md0 + jl) * R + m0 + mh];
    #pragma unroll
    for (int q = 0; q < 4; q++) dst[q] = ((float4*)ob)[q];
}

// ---------------- activation blend (a >= 0) ----------------
__device__ __forceinline__ float blendf(float a, const float* w) {
    const float SELU_SCALE = 1.0507009873554804934f;
    float e = __expf(-a);
    float sig = __fdividef(1.f, 1.f + e);
    float th = tanh_ap(a);
    float gelu = 0.5f * a * (1.f + erff(a * 0.70710678118654752440f));
    float sp = a + __logf(1.f + e);
    float mish = a * tanh_ap(sp);
    return w[0] * sig + w[2] * th + (w[1] + w[3] + SELU_SCALE * w[6]) * a
         + w[4] * a * sig + w[5] * gelu + w[7] * mish;
}

// ---------------- bf16 mma GEMM: CTA 128x128, BK=32, 3-stage, ldmatrix ----------------
// A [2048,K] bf16 row-major; Bt [ncols,K] bf16 row-major. 8 warps, warp tile 32x64.
// Smem per stage: A 8KB + B 8KB; rows 64B, chunk swizzle j ^= (row>>1)&3.
#define BSM_STAGE 16384
#define BSM_TOT   49152

template<int K, int EPI>
__global__ void __launch_bounds__(256, 2)
gemm_bf16(const __nv_bfloat16* __restrict__ Ag, const __nv_bfloat16* __restrict__ Bg,
          const float* __restrict__ bias) {
    extern __shared__ char smem[];
    const uint32_t sb = smem_u32(smem);
    const int tid = threadIdx.x;
    const int lane = tid & 31, wid = tid >> 5;
    const int wm = wid & 3, wn = wid >> 2;
    const int lrow = lane >> 2, lcol = lane & 3;
    const int m0 = blockIdx.y * 128, n0 = blockIdx.x * 128;
    constexpr int NC = K / 32;

    float acc[2][8][4];
    #pragma unroll
    for (int i = 0; i < 2; i++)
        #pragma unroll
        for (int j = 0; j < 8; j++)
            #pragma unroll
            for (int q = 0; q < 4; q++) acc[i][j][q] = 0.f;

    const char* Ab = (const char*)(Ag + (size_t)m0 * K);
    const char* Bb = (const char*)(Bg + (size_t)n0 * K);

    auto load_stage = [&](int c, int buf) {
        int k0b = c * 64;
        uint32_t sA = sb + buf * BSM_STAGE;
        uint32_t sB = sA + 8192;
        #pragma unroll
        for (int i = 0; i < 2; i++) {
            int id = tid + i * 256;
            int r = id >> 2, j = id & 3;
            cp16(sA + r * 64 + ((j ^ ((r >> 1) & 3)) << 4),
                 Ab + (size_t)r * (K * 2) + k0b + j * 16);
        }
        #pragma unroll
        for (int i = 0; i < 2; i++) {
            int id = tid + i * 256;
            int r = id >> 2, j = id & 3;
            cp16(sB + r * 64 + ((j ^ ((r >> 1) & 3)) << 4),
                 Bb + (size_t)r * (K * 2) + k0b + j * 16);
        }
        cp_commit();
    };

    // per-lane ldmatrix address components
    const int matsel = lane >> 3;
    const int arow0 = wm * 32 + (matsel & 1) * 8 + (lane & 7);  // + i*16
    const int akc = matsel >> 1;                                 // k-half chunk
    const int bn0 = wn * 64 + (matsel >> 1) * 8 + (lane & 7);    // + jn*16
    const int bkc = matsel & 1;

    load_stage(0, 0);
    load_stage(1, 1);

    #pragma unroll 1
    for (int c = 0; c < NC; c++) {
        if (c + 1 < NC) cp_wait<1>(); else cp_wait<0>();
        __syncthreads();
        uint32_t sA = sb + (c % 3) * BSM_STAGE;
        uint32_t sB = sA + 8192;
        #pragma unroll
        for (int ks = 0; ks < 2; ks++) {
            uint32_t a[2][4];
            #pragma unroll
            for (int i = 0; i < 2; i++) {
                int row = arow0 + i * 16;
                ldsm4(a[i][0], a[i][1], a[i][2], a[i][3],
                      sA + row * 64 + (((ks * 2 + akc) ^ ((row >> 1) & 3)) << 4));
            }
            uint32_t bfr[8][2];
            #pragma unroll
            for (int jn = 0; jn < 4; jn++) {
                int n = bn0 + jn * 16;
                uint32_t r0, r1, r2, r3;
                ldsm4(r0, r1, r2, r3,
                      sB + n * 64 + (((ks * 2 + bkc) ^ ((n >> 1) & 3)) << 4));
                bfr[jn * 2][0] = r0;     bfr[jn * 2][1] = r1;
                bfr[jn * 2 + 1][0] = r2; bfr[jn * 2 + 1][1] = r3;
            }
            #pragma unroll
            for (int i = 0; i < 2; i++)
                #pragma unroll
                for (int j = 0; j < 8; j++)
                    mma_bf16(acc[i][j], a[i], bfr[j]);
        }
        __syncthreads();
        if (c + 2 < NC) load_stage(c + 2, (c + 2) % 3);
    }

    // ---------------- epilogues ----------------
    if (EPI == 0) {
        float w[8];
        #pragma unroll
        for (int q = 0; q < 8; q++) w[q] = g_wts[q];
        const int cb = (lane & 1) * 2;
        #pragma unroll
        for (int i = 0; i < 2; i++) {
            int r0 = m0 + wm * 32 + i * 16 + lrow;
            int r1 = r0 + 8;
            float gA0 = g_gate[r0 * 4 + cb], gA1 = g_gate[r0 * 4 + cb + 1];
            float gB0 = g_gate[r1 * 4 + cb], gB1 = g_gate[r1 * 4 + cb + 1];
            #pragma unroll
            for (int j = 0; j < 8; j++) {
                int col0 = n0 + wn * 64 + j * 8 + 2 * lcol;
                float bb0 = bias[col0], bb1 = bias[col0 + 1];
                float pl = (acc[i][j][0] + bb0) * gA0 + (acc[i][j][1] + bb1) * gA1;
                float ph = (acc[i][j][2] + bb0) * gB0 + (acc[i][j][3] + bb1) * gB1;
                pl += __shfl_xor_sync(0xFFFFFFFFu, pl, 1);
                ph += __shfl_xor_sync(0xFFFFFFFFu, ph, 1);
                float z = (lane & 1) ? ph : pl;
                int row = (lane & 1) ? r1 : r0;
                int u = (n0 + wn * 64 + j * 8 + (lane & 2) * 2) >> 2;
                float a = fmaxf(z * g_cm[u], 0.f);
                g_blend[(size_t)row * U_ + u] = __float2bfloat16(blendf(a, w));
            }
        }
    } else {
        #pragma unroll
        for (int i = 0; i < 2; i++) {
            int r0 = m0 + wm * 32 + i * 16 + lrow;
            int r1 = r0 + 8;
            #pragma unroll
            for (int j = 0; j < 8; j++) {
                int col0 = n0 + wn * 64 + j * 8 + 2 * lcol;
                float bb0 = bias[col0], bb1 = bias[col0 + 1];
                *(float2*)&g_logits[(size_t)r0 * M_ + col0] =
                    make_float2(acc[i][j][0] + bb0, acc[i][j][1] + bb1);
                *(float2*)&g_logits[(size_t)r1 * M_ + col0] =
                    make_float2(acc[i][j][2] + bb0, acc[i][j][3] + bb1);
            }
        }
    }
}

// ---------------- tf32 GEMM3: attnd @ memt + colmean -> out ----------------
#define GSM_STAGE 16384
#define GSM_BOFF  49152
#define GSM_TOT   98304

__global__ void __launch_bounds__(256, 2)
gemm_tf32_3(const float* __restrict__ A, const float* __restrict__ Bt,
            float* __restrict__ outp) {
    extern __shared__ char smem[];
    const uint32_t sb = smem_u32(smem);
    const int tid = threadIdx.x;
    const int lane = tid & 31, wid = tid >> 5;
    const int wm = wid & 3, wn = wid >> 2;
    const int lrow = lane >> 2, lcol = lane & 3;
    const int m0 = blockIdx.y * 128, n0 = blockIdx.x * 128;
    constexpr int K = M_;
    constexpr int NC = K / 32;

    float acc[2][8][4];
    #pragma unroll
    for (int i = 0; i < 2; i++)
        #pragma unroll
        for (int j = 0; j < 8; j++)
            #pragma unroll
            for (int q = 0; q < 4; q++) acc[i][j][q] = 0.f;

    const float* Ab = A + (size_t)m0 * K;
    const float* Bb = Bt + (size_t)n0 * K;

    auto load_stage = [&](int c, int buf) {
        int k0 = c * 32;
        uint32_t sA = sb + buf * GSM_STAGE;
        uint32_t sB = sb + GSM_BOFF + buf * GSM_STAGE;
        #pragma unroll
        for (int i = 0; i < 4; i++) {
            int id = tid + i * 256;
            int r = id >> 3, cc = id & 7;
            cp16(sA + swz(r * 128 + cc * 16), Ab + (size_t)r * K + k0 + cc * 4);
        }
        #pragma unroll
        for (int i = 0; i < 4; i++) {
            int id = tid + i * 256;
            int r = id >> 3, cc = id & 7;
            cp16(sB + swz(r * 128 + cc * 16), Bb + (size_t)r * K + k0 + cc * 4);
        }
        cp_commit();
    };

    load_stage(0, 0);
    load_stage(1, 1);

    #pragma unroll 1
    for (int c = 0; c < NC; c++) {
        if (c + 1 < NC) cp_wait<1>(); else cp_wait<0>();
        __syncthreads();
        int buf = c % 3;
        uint32_t sA = sb + buf * GSM_STAGE;
        uint32_t sB = sb + GSM_BOFF + buf * GSM_STAGE;
        #pragma unroll
        for (int kk = 0; kk < 4; kk++) {
            uint32_t a[2][4], bf[8][2];
            #pragma unroll
            for (int i = 0; i < 2; i++) {
                int r = wm * 32 + i * 16 + lrow;
                int w = kk * 8 + lcol;
                a[i][0] = lds_u(sA + swz(r * 128 + w * 4));
                a[i][1] = lds_u(sA + swz((r + 8) * 128 + w * 4));
                a[i][2] = lds_u(sA + swz(r * 128 + (w + 4) * 4));
                a[i][3] = lds_u(sA + swz((r + 8) * 128 + (w + 4) * 4));
            }
            #pragma unroll
            for (int j = 0; j < 8; j++) {
                int n = wn * 64 + j * 8 + lrow;
                int w = kk * 8 + lcol;
                bf[j][0] = lds_u(sB + swz(n * 128 + w * 4));
                bf[j][1] = lds_u(sB + swz(n * 128 + (w + 4) * 4));
            }
            #pragma unroll
            for (int i = 0; i < 2; i++)
                #pragma unroll
                for (int j = 0; j < 8; j++)
                    mma_tf32(acc[i][j], a[i], bf[j]);
        }
        __syncthreads();
        if (c + 2 < NC) load_stage(c + 2, (c + 2) % 3);
    }

    // colmean into smem (reuse stage 0)
    float* cms = (float*)smem;
    if (tid < 128) {
        float s = 0.f;
        #pragma unroll
        for (int p = 0; p < 8; p++) s += g_cmpart[p * MD_ + n0 + tid];
        cms[tid] = s * (1.f / (float)M_);
    }
    __syncthreads();

    #pragma unroll
    for (int i = 0; i < 2; i++) {
        int r0 = m0 + wm * 32 + i * 16 + lrow;
        int r1 = r0 + 8;
        #pragma unroll
        for (int j = 0; j < 8; j++) {
            int col0 = n0 + wn * 64 + j * 8 + 2 * lcol;
            float cm0 = cms[col0 - n0], cm1 = cms[col0 + 1 - n0];
            *(float2*)&outp[(size_t)r0 * MD_ + col0] =
                make_float2(acc[i][j][0] + cm0, acc[i][j][1] + cm1);
            *(float2*)&outp[(size_t)r1 * MD_ + col0] =
                make_float2(acc[i][j][2] + cm0, acc[i][j][3] + cm1);
        }
    }
}

// ---------------- softmax: fp32 logits -> tf32-rounded (attn - 1/M) ----------------
__global__ void __launch_bounds__(256) k_softmax() {
    __shared__ float sm[256];
    int n = blockIdx.x, t = threadIdx.x;
    const float4* row4 = (const float4*)&g_logits[(size_t)n * M_];
    float4 v[8];
    float mx = -3.4e38f;
    #pragma unroll
    for (int i = 0; i < 8; i++) {
        v[i] = row4[t + i * 256];
        mx = fmaxf(mx, fmaxf(fmaxf(v[i].x, v[i].y), fmaxf(v[i].z, v[i].w)));
    }
    sm[t] = mx; __syncthreads();
    for (int o = 128; o > 0; o >>= 1) {
        if (t < o) sm[t] = fmaxf(sm[t], sm[t + o]);
        __syncthreads();
    }
    mx = sm[0]; __syncthreads();
    float s = 0.f;
    #pragma unroll
    for (int i = 0; i < 8; i++) {
        v[i].x = expf(v[i].x - mx); v[i].y = expf(v[i].y - mx);
        v[i].z = expf(v[i].z - mx); v[i].w = expf(v[i].w - mx);
        s += v[i].x + v[i].y + v[i].z + v[i].w;
    }
    sm[t] = s; __syncthreads();
    for (int o = 128; o > 0; o >>= 1) {
        if (t < o) sm[t] += sm[t + o];
        __syncthreads();
    }
    float inv = 1.f / sm[0];
    const float im = 1.f / (float)M_;
    float4* dst = (float4*)&g_attnd[(size_t)n * M_];
    #pragma unroll
    for (int i = 0; i < 8; i++) {
        dst[t + i * 256] = make_float4(
            rna_tf32(v[i].x * inv - im), rna_tf32(v[i].y * inv - im),
            rna_tf32(v[i].z * inv - im), rna_tf32(v[i].w * inv - im));
    }
}

// ---------------- launch ----------------
extern "C" void kernel_launch(void* const* d_in, const int* in_sizes, int n_in,
                              void* d_out, int out_size) {
    const float* x        = (const float*)d_in[0];
    const float* w        = (const float*)d_in[1];
    const float* delay    = (const float*)d_in[2];
    const float* b        = (const float*)d_in[3];
    const float* gate_W   = (const float*)d_in[4];
    const float* gate_b   = (const float*)d_in[5];
    const float* navg     = (const float*)d_in[6];
    const float* conn_W1  = (const float*)d_in[7];
    const float* conn_b1  = (const float*)d_in[8];
    const float* conn_W2  = (const float*)d_in[9];
    const float* conn_b2  = (const float*)d_in[10];
    const float* mask     = (const float*)d_in[11];
    const float* act_w    = (const float*)d_in[12];
    const float* read_W   = (const float*)d_in[13];
    const float* read_b   = (const float*)d_in[14];
    const float* memory   = (const float*)d_in[15];
    float* out = (float*)d_out;

    __nv_bfloat16 *p_xbf, *p_wct, *p_rwt, *p_blend;
    float *p_memt, *p_attnd;
    cudaGetSymbolAddress((void**)&p_xbf, g_xbf);
    cudaGetSymbolAddress((void**)&p_wct, g_wct);
    cudaGetSymbolAddress((void**)&p_rwt, g_rwt);
    cudaGetSymbolAddress((void**)&p_blend, g_blend);
    cudaGetSymbolAddress((void**)&p_memt, g_memt);
    cudaGetSymbolAddress((void**)&p_attnd, g_attnd);

    cudaFuncSetAttribute(gemm_bf16<D_, 0>, cudaFuncAttributeMaxDynamicSharedMemorySize, BSM_TOT);
    cudaFuncSetAttribute(gemm_bf16<U_, 1>, cudaFuncAttributeMaxDynamicSharedMemorySize, BSM_TOT);
    cudaFuncSetAttribute(gemm_tf32_3, cudaFuncAttributeMaxDynamicSharedMemorySize, GSM_TOT);

    // 1: misc (gate/conn/actw/colsums)
    k_misc<<<N_ + 2 + 256, 256>>>(x, gate_W, gate_b, navg, conn_W1, conn_b1,
                                  conn_W2, conn_b2, mask, act_w, memory);
    // 2: x -> bf16
    k_cvt_x<<<2048, 256>>>((const float4*)x);
    // 3: (w * sigmoid(delay))^T -> bf16
    k_prep_wct<<<dim3(64, 32), 256>>>(w, delay);
    // 4: GEMM1 (profiled)
    gemm_bf16<D_, 0><<<dim3(64, 16), 256, BSM_TOT>>>(p_xbf, p_wct, b);
    // 5: read_W^T -> bf16
    k_prep_rwt<<<dim3(64, 64), 256>>>(read_W);
    // 6: GEMM2 -> logits
    gemm_bf16<U_, 1><<<dim3(64, 16), 256, BSM_TOT>>>(p_blend, p_rwt, read_b);
    // 7: softmax -> attnd (tf32-rounded)
    k_softmax<<<N_, 256>>>();
    // 8: memory^T (tf32-rounded)
    k_prep_memt<<<dim3(8, 256), 256>>>(memory);
    // 9: GEMM3 -> out
    gemm_tf32_3<<<dim3(8, 16), 256, GSM_TOT>>>(p_attnd, p_memt, out);
}

// round 7
// speedup vs baseline: 7.1129x; 1.3159x over previous
#include <cuda_runtime.h>
#include <cuda_bf16.h>
#include <math.h>
#include <stdint.h>

#define N_  2048
#define D_  1024
#define U_  2048
#define NB_ 4
#define M_  8192
#define MD_ 1024

// ---------------- scratch (device globals; no allocs allowed) ----------------
__device__ __align__(16) __nv_bfloat16 g_xbf[(size_t)N_ * D_];        // x bf16
__device__ __align__(16) __nv_bfloat16 g_wct[(size_t)U_ * NB_ * D_];  // (w*sig)^T bf16
__device__ __align__(16) __nv_bfloat16 g_rwt[(size_t)M_ * U_];        // read_W^T bf16
__device__ __align__(16) __nv_bfloat16 g_memt[(size_t)MD_ * M_];      // memory^T bf16
__device__ __align__(16) __nv_bfloat16 g_blend[(size_t)N_ * U_];      // bf16
__device__ __align__(16) float g_logits[(size_t)N_ * M_];             // fp32
__device__ __align__(16) __nv_bfloat16 g_attnd[(size_t)N_ * M_];      // (attn-1/M) bf16
__device__ float g_cmpart[8 * MD_];                                   // colsum partials (fp32)
__device__ float g_gate[N_ * NB_];
__device__ float g_cm[U_];
__device__ float g_wts[8];

// ---------------- PTX helpers ----------------
__device__ __forceinline__ uint32_t smem_u32(const void* p) {
    uint32_t a;
    asm("{ .reg .u64 t; cvta.to.shared.u64 t, %1; cvt.u32.u64 %0, t; }" : "=r"(a) : "l"(p));
    return a;
}
__device__ __forceinline__ void cp16(uint32_t s, const void* g) {
    asm volatile("cp.async.cg.shared.global [%0], [%1], 16;" :: "r"(s), "l"(g));
}
__device__ __forceinline__ void cp_commit() { asm volatile("cp.async.commit_group;"); }
template<int NN> __device__ __forceinline__ void cp_wait() {
    asm volatile("cp.async.wait_group %0;" :: "n"(NN));
}
__device__ __forceinline__ void ldsm4(uint32_t& r0, uint32_t& r1, uint32_t& r2, uint32_t& r3,
                                      uint32_t a) {
    asm volatile("ldmatrix.sync.aligned.m8n8.x4.shared.b16 {%0,%1,%2,%3}, [%4];"
                 : "=r"(r0), "=r"(r1), "=r"(r2), "=r"(r3) : "r"(a));
}
__device__ __forceinline__ void mma_bf16(float* c, const uint32_t* a, const uint32_t* b) {
    asm volatile(
        "mma.sync.aligned.m16n8k16.row.col.f32.bf16.bf16.f32 "
        "{%0,%1,%2,%3}, {%4,%5,%6,%7}, {%8,%9}, {%0,%1,%2,%3};"
        : "+f"(c[0]), "+f"(c[1]), "+f"(c[2]), "+f"(c[3])
        : "r"(a[0]), "r"(a[1]), "r"(a[2]), "r"(a[3]), "r"(b[0]), "r"(b[1]));
}
__device__ __forceinline__ float sigmoidf_(float x) { return 1.f / (1.f + expf(-x)); }
__device__ __forceinline__ float tanh_ap(float x) {
    float r;
    asm("tanh.approx.f32 %0, %1;" : "=f"(r) : "f"(x));
    return r;
}

// ---------------- k_misc: gate softmax + conn + act weights + colsum partials ----------
__global__ void __launch_bounds__(256) k_misc(
    const float* __restrict__ x, const float* __restrict__ gW, const float* __restrict__ gb,
    const float* __restrict__ na, const float* __restrict__ W1, const float* __restrict__ b1,
    const float* __restrict__ W2, const float* __restrict__ b2, const float* __restrict__ mask,
    const float* __restrict__ aw, const float* __restrict__ mem) {
    __shared__ float4 sh4[256];
    __shared__ float red[256];
    __shared__ float h32[32];
    int bid = blockIdx.x, t = threadIdx.x;
    if (bid < N_) {
        float4 s = make_float4(0.f, 0.f, 0.f, 0.f);
        #pragma unroll
        for (int i = 0; i < 4; i++) {
            int d = t + i * 256;
            float xv = x[bid * D_ + d];
            float4 g = *(const float4*)&gW[d * 4];
            s.x += xv * g.x; s.y += xv * g.y; s.z += xv * g.z; s.w += xv * g.w;
        }
        sh4[t] = s;
        __syncthreads();
        for (int o = 128; o > 0; o >>= 1) {
            if (t < o) {
                sh4[t].x += sh4[t + o].x; sh4[t].y += sh4[t + o].y;
                sh4[t].z += sh4[t + o].z; sh4[t].w += sh4[t + o].w;
            }
            __syncthreads();
        }
        if (t == 0) {
            float4 v = sh4[0];
            float l0 = v.x + gb[0], l1 = v.y + gb[1], l2 = v.z + gb[2], l3 = v.w + gb[3];
            float mx = fmaxf(fmaxf(l0, l1), fmaxf(l2, l3));
            float e0 = expf(l0 - mx), e1 = expf(l1 - mx), e2 = expf(l2 - mx), e3 = expf(l3 - mx);
            float inv = 1.f / (e0 + e1 + e2 + e3);
            *(float4*)&g_gate[bid * 4] = make_float4(e0 * inv, e1 * inv, e2 * inv, e3 * inv);
        }
    } else if (bid == N_) {
        int j = t >> 3, l = t & 7;
        float p = 0.f;
        for (int u = l; u < U_; u += 8) p += na[u] * W1[u * 32 + j];
        red[t] = p;
        __syncthreads();
        if (l == 0) {
            float s = 0.f;
            for (int q = 0; q < 8; q++) s += red[j * 8 + q];
            h32[j] = fmaxf(s + b1[j], 0.f);
        }
        __syncthreads();
        for (int u = t; u < U_; u += 256) {
            float s = b2[u];
            #pragma unroll
            for (int jj = 0; jj < 32; jj++) s += h32[jj] * W2[jj * U_ + u];
            g_cm[u] = mask[u] * sigmoidf_(s);
        }
    } else if (bid == N_ + 1) {
        if (t == 0) {
            float m = -1e30f;
            for (int i = 0; i < 9; i++) m = fmaxf(m, aw[i]);
            float e[9], s = 0.f;
            for (int i = 0; i < 9; i++) { e[i] = expf(aw[i] - m); s += e[i]; }
            float inv = 1.f / s;
            for (int i = 0; i < 8; i++) g_wts[i] = e[i] * inv;
        }
    } else {
        int bc = bid - (N_ + 2);
        int rc = bc >> 5, cc = bc & 31;
        int c = cc * 32 + (t & 31), ty = t >> 5;
        float s = 0.f;
        const float* p = mem + (size_t)(rc * 1024 + ty) * MD_ + c;
        #pragma unroll 4
        for (int i = 0; i < 128; i++) s += p[(size_t)i * 8 * MD_];
        red[t] = s;
        __syncthreads();
        if (ty == 0) {
            float tot = 0.f;
            #pragma unroll
            for (int q = 0; q < 8; q++) tot += red[q * 32 + (t & 31)];
            g_cmpart[rc * MD_ + c] = tot;
        }
    }
}

// ---------------- x -> bf16 ----------------
__global__ void k_cvt_x(const float4* __restrict__ x) {
    int i = blockIdx.x * blockDim.x + threadIdx.x;
    float4 v = x[i];
    __nv_bfloat162* o = (__nv_bfloat162*)g_xbf;
    o[i * 2 + 0] = __floats2bfloat162_rn(v.x, v.y);
    o[i * 2 + 1] = __floats2bfloat162_rn(v.z, v.w);
}

// ---------------- w*sigmoid(delay) transpose -> bf16 ----------------
__global__ void __launch_bounds__(256) k_prep_wct(const float* __restrict__ w,
                                                  const float* __restrict__ delay) {
    __shared__ float tbuf[32][129];
    const int C = U_ * NB_;
    int j0 = blockIdx.x * 128, d0 = blockIdx.y * 32;
    int tx = threadIdx.x & 31, ty = threadIdx.x >> 5;
    #pragma unroll
    for (int i = 0; i < 4; i++) {
        int r = ty + i * 8;
        size_t idx = (size_t)(d0 + r) * C + j0 + tx * 4;
        float4 wv = *(const float4*)&w[idx];
        float4 dv = *(const float4*)&delay[idx];
        tbuf[r][tx * 4 + 0] = wv.x * sigmoidf_(dv.x);
        tbuf[r][tx * 4 + 1] = wv.y * sigmoidf_(dv.y);
        tbuf[r][tx * 4 + 2] = wv.z * sigmoidf_(dv.z);
        tbuf[r][tx * 4 + 3] = wv.w * sigmoidf_(dv.w);
    }
    __syncthreads();
    int jl = threadIdx.x >> 1, dh = (threadIdx.x & 1) << 4;
    __align__(16) __nv_bfloat16 ob[16];
    #pragma unroll
    for (int q = 0; q < 16; q++) ob[q] = __float2bfloat16(tbuf[dh + q][jl]);
    uint4* dst = (uint4*)&g_wct[(size_t)(j0 + jl) * D_ + d0 + dh];
    dst[0] = ((uint4*)ob)[0];
    dst[1] = ((uint4*)ob)[1];
}

// ---------------- generic fp32 [R,C] -> bf16 transpose [C,R] ----------------
__global__ void __launch_bounds__(256) k_prep_t(const float* __restrict__ src,
                                                __nv_bfloat16* __restrict__ dst,
                                                int R, int C) {
    __shared__ float tbuf[32][129];
    int j0 = blockIdx.x * 128, r0 = blockIdx.y * 32;
    int tx = threadIdx.x & 31, ty = threadIdx.x >> 5;
    #pragma unroll
    for (int i = 0; i < 4; i++) {
        int r = ty + i * 8;
        float4 v = *(const float4*)&src[(size_t)(r0 + r) * C + j0 + tx * 4];
        tbuf[r][tx * 4 + 0] = v.x; tbuf[r][tx * 4 + 1] = v.y;
        tbuf[r][tx * 4 + 2] = v.z; tbuf[r][tx * 4 + 3] = v.w;
    }
    __syncthreads();
    int jl = threadIdx.x >> 1, rh = (threadIdx.x & 1) << 4;
    __align__(16) __nv_bfloat16 ob[16];
    #pragma unroll
    for (int q = 0; q < 16; q++) ob[q] = __float2bfloat16(tbuf[rh + q][jl]);
    uint4* d4 = (uint4*)&dst[(size_t)(j0 + jl) * R + r0 + rh];
    d4[0] = ((uint4*)ob)[0];
    d4[1] = ((uint4*)ob)[1];
}

// ---------------- activation blend (a >= 0) ----------------
__device__ __forceinline__ float blendf(float a, const float* w) {
    const float SELU_SCALE = 1.0507009873554804934f;
    float e = __expf(-a);
    float sig = __fdividef(1.f, 1.f + e);
    float th = tanh_ap(a);
    float gelu = 0.5f * a * (1.f + erff(a * 0.70710678118654752440f));
    float sp = a + __logf(1.f + e);
    float mish = a * tanh_ap(sp);
    return w[0] * sig + w[2] * th + (w[1] + w[3] + SELU_SCALE * w[6]) * a
         + w[4] * a * sig + w[5] * gelu + w[7] * mish;
}

// ---------------- bf16 mma GEMM: CTA (MW*32)x128, BK=32, 3-stage cp.async -----------
// A [2048,K] bf16 row-major; Bt [ncols,K] bf16 row-major. MW*2 warps, warp tile 32x64.
// Hoisted swizzled offsets; slice1 addr = slice0 ^ 0x20; one barrier per chunk;
// cp.async for chunk c+2 issued before compute of chunk c.
template<int K, int EPI, int MW>
__global__ void __launch_bounds__(MW * 64, 8 / MW)
gemm_bf16(const __nv_bfloat16* __restrict__ Ag, const __nv_bfloat16* __restrict__ Bg,
          const float* __restrict__ bias, float* __restrict__ outp) {
    constexpr int NTH    = MW * 64;
    constexpr int ABYTES = MW * 32 * 64;
    constexpr int STAGE  = ABYTES + 8192;
    constexpr int NBCP   = 512 / NTH;
    constexpr int NC     = K / 32;

    extern __shared__ char smem[];
    const uint32_t sb = smem_u32(smem);
    const int tid = threadIdx.x;
    const int lane = tid & 31, wid = tid >> 5;
    const int wm = wid & (MW - 1), wn = wid / MW;
    const int lrow = lane >> 2, lcol = lane & 3;
    const int m0 = blockIdx.y * (MW * 32), n0 = blockIdx.x * 128;

    float acc[2][8][4];
    #pragma unroll
    for (int i = 0; i < 2; i++)
        #pragma unroll
        for (int j = 0; j < 8; j++)
            #pragma unroll
            for (int q = 0; q < 4; q++) acc[i][j][q] = 0.f;

    // cp.async loop-invariant offsets
    const char* baseA = (const char*)(Ag + (size_t)m0 * K);
    const char* baseB = (const char*)(Bg + (size_t)n0 * K);
    uint32_t ago[2], asmo[2], bgo[NBCP], bsmo[NBCP];
    #pragma unroll
    for (int i = 0; i < 2; i++) {
        int id = tid + i * NTH, r = id >> 2, j = id & 3;
        ago[i] = r * (K * 2) + j * 16;
        asmo[i] = r * 64 + ((j ^ ((r >> 1) & 3)) << 4);
    }
    #pragma unroll
    for (int i = 0; i < NBCP; i++) {
        int id = tid + i * NTH, r = id >> 2, j = id & 3;
        bgo[i] = r * (K * 2) + j * 16;
        bsmo[i] = r * 64 + ((j ^ ((r >> 1) & 3)) << 4);
    }

    // ldmatrix loop-invariant offsets (slice 0; slice 1 = ^0x20)
    const int matsel = lane >> 3;
    uint32_t aoff[2], boff[4];
    #pragma unroll
    for (int i = 0; i < 2; i++) {
        int row = wm * 32 + (matsel & 1) * 8 + (lane & 7) + i * 16;
        int akc = matsel >> 1;
        aoff[i] = row * 64 + ((akc ^ ((row >> 1) & 3)) << 4);
    }
    #pragma unroll
    for (int jn = 0; jn < 4; jn++) {
        int n = wn * 64 + (matsel >> 1) * 8 + (lane & 7) + jn * 16;
        int bkc = matsel & 1;
        boff[jn] = n * 64 + ((bkc ^ ((n >> 1) & 3)) << 4);
    }

    auto load_stage = [&](int sidx) {
        uint32_t sA = sb + sidx * STAGE, sB = sA + ABYTES;
        #pragma unroll
        for (int i = 0; i < 2; i++) cp16(sA + asmo[i], baseA + ago[i]);
        #pragma unroll
        for (int i = 0; i < NBCP; i++) cp16(sB + bsmo[i], baseB + bgo[i]);
        cp_commit();
        baseA += 64; baseB += 64;
    };
    load_stage(0);
    load_stage(1);

    #pragma unroll 1
    for (int c = 0; c < NC; c++) {
        if (c + 2 < NC) cp_wait<1>(); else cp_wait<0>();
        __syncthreads();
        if (c + 2 < NC) load_stage((c + 2) % 3);
        uint32_t sA = sb + (c % 3) * STAGE, sB = sA + ABYTES;

        uint32_t a0[2][4], a1[2][4], bfr[8][2];
        #pragma unroll
        for (int i = 0; i < 2; i++)
            ldsm4(a0[i][0], a0[i][1], a0[i][2], a0[i][3], sA + aoff[i]);
        #pragma unroll
        for (int jn = 0; jn < 4; jn++) {
            uint32_t r0, r1, r2, r3;
            ldsm4(r0, r1, r2, r3, sB + boff[jn]);
            bfr[2 * jn][0] = r0;     bfr[2 * jn][1] = r1;
            bfr[2 * jn + 1][0] = r2; bfr[2 * jn + 1][1] = r3;
        }
        #pragma unroll
        for (int i = 0; i < 2; i++)
            ldsm4(a1[i][0], a1[i][1], a1[i][2], a1[i][3], sA + (aoff[i] ^ 0x20u));
        #pragma unroll
        for (int i = 0; i < 2; i++)
            #pragma unroll
            for (int j = 0; j < 8; j++)
                mma_bf16(acc[i][j], a0[i], bfr[j]);
        #pragma unroll
        for (int jn = 0; jn < 4; jn++) {
            uint32_t r0, r1, r2, r3;
            ldsm4(r0, r1, r2, r3, sB + (boff[jn] ^ 0x20u));
            bfr[2 * jn][0] = r0;     bfr[2 * jn][1] = r1;
            bfr[2 * jn + 1][0] = r2; bfr[2 * jn + 1][1] = r3;
        }
        #pragma unroll
        for (int i = 0; i < 2; i++)
            #pragma unroll
            for (int j = 0; j < 8; j++)
                mma_bf16(acc[i][j], a1[i], bfr[j]);
    }

    // ---------------- epilogues ----------------
    if (EPI == 0) {
        float w[8];
        #pragma unroll
        for (int q = 0; q < 8; q++) w[q] = g_wts[q];
        const int cb = (lane & 1) * 2;
        #pragma unroll
        for (int i = 0; i < 2; i++) {
            int r0 = m0 + wm * 32 + i * 16 + lrow;
            int r1 = r0 + 8;
            float gA0 = g_gate[r0 * 4 + cb], gA1 = g_gate[r0 * 4 + cb + 1];
            float gB0 = g_gate[r1 * 4 + cb], gB1 = g_gate[r1 * 4 + cb + 1];
            #pragma unroll
            for (int j = 0; j < 8; j++) {
                int col0 = n0 + wn * 64 + j * 8 + 2 * lcol;
                float bb0 = bias[col0], bb1 = bias[col0 + 1];
                float pl = (acc[i][j][0] + bb0) * gA0 + (acc[i][j][1] + bb1) * gA1;
                float ph = (acc[i][j][2] + bb0) * gB0 + (acc[i][j][3] + bb1) * gB1;
                pl += __shfl_xor_sync(0xFFFFFFFFu, pl, 1);
                ph += __shfl_xor_sync(0xFFFFFFFFu, ph, 1);
                float z = (lane & 1) ? ph : pl;
                int row = (lane & 1) ? r1 : r0;
                int u = (n0 + wn * 64 + j * 8 + (lane & 2) * 2) >> 2;
                float a = fmaxf(z * g_cm[u], 0.f);
                g_blend[(size_t)row * U_ + u] = __float2bfloat16(blendf(a, w));
            }
        }
    } else if (EPI == 1) {
        #pragma unroll
        for (int i = 0; i < 2; i++) {
            int r0 = m0 + wm * 32 + i * 16 + lrow;
            int r1 = r0 + 8;
            #pragma unroll
            for (int j = 0; j < 8; j++) {
                int col0 = n0 + wn * 64 + j * 8 + 2 * lcol;
                float bb0 = bias[col0], bb1 = bias[col0 + 1];
                *(float2*)&g_logits[(size_t)r0 * M_ + col0] =
                    make_float2(acc[i][j][0] + bb0, acc[i][j][1] + bb1);
                *(float2*)&g_logits[(size_t)r1 * M_ + col0] =
                    make_float2(acc[i][j][2] + bb0, acc[i][j][3] + bb1);
            }
        }
    } else {
        __syncthreads();
        float* cms = (float*)smem;
        if (tid < 128) {
            float s = 0.f;
            #pragma unroll
            for (int p = 0; p < 8; p++) s += g_cmpart[p * MD_ + n0 + tid];
            cms[tid] = s * (1.f / (float)M_);
        }
        __syncthreads();
        #pragma unroll
        for (int i = 0; i < 2; i++) {
            int r0 = m0 + wm * 32 + i * 16 + lrow;
            int r1 = r0 + 8;
            #pragma unroll
            for (int j = 0; j < 8; j++) {
                int col0 = n0 + wn * 64 + j * 8 + 2 * lcol;
                float cm0 = cms[col0 - n0], cm1 = cms[col0 + 1 - n0];
                *(float2*)&outp[(size_t)r0 * MD_ + col0] =
                    make_float2(acc[i][j][0] + cm0, acc[i][j][1] + cm1);
                *(float2*)&outp[(size_t)r1 * MD_ + col0] =
                    make_float2(acc[i][j][2] + cm0, acc[i][j][3] + cm1);
            }
        }
    }
}

// ---------------- softmax: fp32 logits -> bf16 (attn - 1/M) ----------------
__global__ void __launch_bounds__(256) k_softmax() {
    __shared__ float sm[256];
    int n = blockIdx.x, t = threadIdx.x;
    const float4* row4 = (const float4*)&g_logits[(size_t)n * M_];
    float4 v[8];
    float mx = -3.4e38f;
    #pragma unroll
    for (int i = 0; i < 8; i++) {
        v[i] = row4[t + i * 256];
        mx = fmaxf(mx, fmaxf(fmaxf(v[i].x, v[i].y), fmaxf(v[i].z, v[i].w)));
    }
    sm[t] = mx; __syncthreads();
    for (int o = 128; o > 0; o >>= 1) {
        if (t < o) sm[t] = fmaxf(sm[t], sm[t + o]);
        __syncthreads();
    }
    mx = sm[0]; __syncthreads();
    float s = 0.f;
    #pragma unroll
    for (int i = 0; i < 8; i++) {
        v[i].x = expf(v[i].x - mx); v[i].y = expf(v[i].y - mx);
        v[i].z = expf(v[i].z - mx); v[i].w = expf(v[i].w - mx);
        s += v[i].x + v[i].y + v[i].z + v[i].w;
    }
    sm[t] = s; __syncthreads();
    for (int o = 128; o > 0; o >>= 1) {
        if (t < o) sm[t] += sm[t + o];
        __syncthreads();
    }
    float inv = 1.f / sm[0];
    const float im = 1.f / (float)M_;
    uint2* dst = (uint2*)&g_attnd[(size_t)n * M_];
    #pragma unroll
    for (int i = 0; i < 8; i++) {
        uint2 o;
        __nv_bfloat162* h = (__nv_bfloat162*)&o;
        h[0] = __floats2bfloat162_rn(v[i].x * inv - im, v[i].y * inv - im);
        h[1] = __floats2bfloat162_rn(v[i].z * inv - im, v[i].w * inv - im);
        dst[t + i * 256] = o;
    }
}

// ---------------- launch ----------------
extern "C" void kernel_launch(void* const* d_in, const int* in_sizes, int n_in,
                              void* d_out, int out_size) {
    const float* x        = (const float*)d_in[0];
    const float* w        = (const float*)d_in[1];
    const float* delay    = (const float*)d_in[2];
    const float* b        = (const float*)d_in[3];
    const float* gate_W   = (const float*)d_in[4];
    const float* gate_b   = (const float*)d_in[5];
    const float* navg     = (const float*)d_in[6];
    const float* conn_W1  = (const float*)d_in[7];
    const float* conn_b1  = (const float*)d_in[8];
    const float* conn_W2  = (const float*)d_in[9];
    const float* conn_b2  = (const float*)d_in[10];
    const float* mask     = (const float*)d_in[11];
    const float* act_w    = (const float*)d_in[12];
    const float* read_W   = (const float*)d_in[13];
    const float* read_b   = (const float*)d_in[14];
    const float* memory   = (const float*)d_in[15];
    float* out = (float*)d_out;

    __nv_bfloat16 *p_xbf, *p_wct, *p_rwt, *p_memt, *p_blend, *p_attnd;
    cudaGetSymbolAddress((void**)&p_xbf, g_xbf);
    cudaGetSymbolAddress((void**)&p_wct, g_wct);
    cudaGetSymbolAddress((void**)&p_rwt, g_rwt);
    cudaGetSymbolAddress((void**)&p_memt, g_memt);
    cudaGetSymbolAddress((void**)&p_blend, g_blend);
    cudaGetSymbolAddress((void**)&p_attnd, g_attnd);

    cudaFuncSetAttribute(gemm_bf16<D_, 0, 4>, cudaFuncAttributeMaxDynamicSharedMemorySize, 49152);
    cudaFuncSetAttribute(gemm_bf16<U_, 1, 4>, cudaFuncAttributeMaxDynamicSharedMemorySize, 49152);
    cudaFuncSetAttribute(gemm_bf16<M_, 2, 2>, cudaFuncAttributeMaxDynamicSharedMemorySize, 36864);

    // 1: misc (gate/conn/actw/colsums)
    k_misc<<<N_ + 2 + 256, 256>>>(x, gate_W, gate_b, navg, conn_W1, conn_b1,
                                  conn_W2, conn_b2, mask, act_w, memory);
    // 2: x -> bf16
    k_cvt_x<<<2048, 256>>>((const float4*)x);
    // 3: (w*sigmoid(delay))^T -> bf16
    k_prep_wct<<<dim3(64, 32), 256>>>(w, delay);
    // 4: GEMM1 (profiled slot)
    gemm_bf16<D_, 0, 4><<<dim3(64, 16), 256, 49152>>>(p_xbf, p_wct, b, nullptr);
    // 5: read_W^T -> bf16
    k_prep_t<<<dim3(64, 64), 256>>>(read_W, p_rwt, U_, M_);
    // 6: GEMM2 -> logits (fp32)
    gemm_bf16<U_, 1, 4><<<dim3(64, 16), 256, 49152>>>(p_blend, p_rwt, read_b, nullptr);
    // 7: softmax -> attnd (bf16)
    k_softmax<<<N_, 256>>>();
    // 8: memory^T -> bf16
    k_prep_t<<<dim3(8, 256), 256>>>(memory, p_memt, M_, MD_);
    // 9: GEMM3 -> out (+ colmean)
    gemm_bf16<M_, 2, 2><<<dim3(8, 32), 128, 36864>>>(p_attnd, p_memt, nullptr, out);
}

// round 9
// speedup vs baseline: 7.6347x; 1.0734x over previous
#include <cuda_runtime.h>
#include <cuda_bf16.h>
#include <math.h>
#include <stdint.h>

#define N_  2048
#define D_  1024
#define U_  2048
#define NB_ 4
#define M_  8192
#define MD_ 1024

// ---------------- scratch (device globals; no allocs allowed) ----------------
__device__ __align__(16) __nv_bfloat16 g_xbf[(size_t)N_ * D_];        // x bf16 [N,D]
__device__ __align__(16) __nv_bfloat16 g_wcb[(size_t)D_ * U_ * NB_];  // w*sig(delay) bf16 [D,8192]
__device__ __align__(16) __nv_bfloat16 g_rwb[(size_t)U_ * M_];        // read_W bf16 [U,M]
__device__ __align__(16) __nv_bfloat16 g_memb[(size_t)M_ * MD_];      // memory bf16 [M,MD]
__device__ __align__(16) __nv_bfloat16 g_blend[(size_t)N_ * U_];      // bf16 [N,U]
__device__ __align__(16) float g_logits[(size_t)N_ * M_];             // fp32
__device__ __align__(16) __nv_bfloat16 g_attnd[(size_t)N_ * M_];      // (attn-1/M) bf16
__device__ float g_cmpart[8 * MD_];                                   // colsum partials
__device__ float g_gate[N_ * NB_];
__device__ float g_cm[U_];
__device__ float g_wts[8];

// ---------------- PTX helpers ----------------
__device__ __forceinline__ uint32_t smem_u32(const void* p) {
    uint32_t a;
    asm("{ .reg .u64 t; cvta.to.shared.u64 t, %1; cvt.u32.u64 %0, t; }" : "=r"(a) : "l"(p));
    return a;
}
__device__ __forceinline__ void cp16(uint32_t s, const void* g) {
    asm volatile("cp.async.cg.shared.global [%0], [%1], 16;" :: "r"(s), "l"(g));
}
__device__ __forceinline__ void cp_commit() { asm volatile("cp.async.commit_group;"); }
template<int NN> __device__ __forceinline__ void cp_wait() {
    asm volatile("cp.async.wait_group %0;" :: "n"(NN));
}
__device__ __forceinline__ void ldsm4(uint32_t& r0, uint32_t& r1, uint32_t& r2, uint32_t& r3,
                                      uint32_t a) {
    asm volatile("ldmatrix.sync.aligned.m8n8.x4.shared.b16 {%0,%1,%2,%3}, [%4];"
                 : "=r"(r0), "=r"(r1), "=r"(r2), "=r"(r3) : "r"(a));
}
__device__ __forceinline__ void ldsm4t(uint32_t& r0, uint32_t& r1, uint32_t& r2, uint32_t& r3,
                                       uint32_t a) {
    asm volatile("ldmatrix.sync.aligned.m8n8.x4.trans.shared.b16 {%0,%1,%2,%3}, [%4];"
                 : "=r"(r0), "=r"(r1), "=r"(r2), "=r"(r3) : "r"(a));
}
__device__ __forceinline__ void mma_bf16(float* c, const uint32_t* a, const uint32_t* b) {
    asm volatile(
        "mma.sync.aligned.m16n8k16.row.col.f32.bf16.bf16.f32 "
        "{%0,%1,%2,%3}, {%4,%5,%6,%7}, {%8,%9}, {%0,%1,%2,%3};"
        : "+f"(c[0]), "+f"(c[1]), "+f"(c[2]), "+f"(c[3])
        : "r"(a[0]), "r"(a[1]), "r"(a[2]), "r"(a[3]), "r"(b[0]), "r"(b[1]));
}
__device__ __forceinline__ float sigmoidf_(float x) { return 1.f / (1.f + expf(-x)); }
__device__ __forceinline__ float tanh_ap(float x) {
    float r;
    asm("tanh.approx.f32 %0, %1;" : "=f"(r) : "f"(x));
    return r;
}

// ---------------- k_misc: gate softmax + conn + act weights + colsum partials ----------
__global__ void __launch_bounds__(256) k_misc(
    const float* __restrict__ x, const float* __restrict__ gW, const float* __restrict__ gb,
    const float* __restrict__ na, const float* __restrict__ W1, const float* __restrict__ b1,
    const float* __restrict__ W2, const float* __restrict__ b2, const float* __restrict__ mask,
    const float* __restrict__ aw, const float* __restrict__ mem) {
    __shared__ float4 sh4[256];
    __shared__ float red[256];
    __shared__ float h32[32];
    int bid = blockIdx.x, t = threadIdx.x;
    if (bid < N_) {
        float4 s = make_float4(0.f, 0.f, 0.f, 0.f);
        #pragma unroll
        for (int i = 0; i < 4; i++) {
            int d = t + i * 256;
            float xv = x[bid * D_ + d];
            float4 g = *(const float4*)&gW[d * 4];
            s.x += xv * g.x; s.y += xv * g.y; s.z += xv * g.z; s.w += xv * g.w;
        }
        sh4[t] = s;
        __syncthreads();
        for (int o = 128; o > 0; o >>= 1) {
            if (t < o) {
                sh4[t].x += sh4[t + o].x; sh4[t].y += sh4[t + o].y;
                sh4[t].z += sh4[t + o].z; sh4[t].w += sh4[t + o].w;
            }
            __syncthreads();
        }
        if (t == 0) {
            float4 v = sh4[0];
            float l0 = v.x + gb[0], l1 = v.y + gb[1], l2 = v.z + gb[2], l3 = v.w + gb[3];
            float mx = fmaxf(fmaxf(l0, l1), fmaxf(l2, l3));
            float e0 = expf(l0 - mx), e1 = expf(l1 - mx), e2 = expf(l2 - mx), e3 = expf(l3 - mx);
            float inv = 1.f / (e0 + e1 + e2 + e3);
            *(float4*)&g_gate[bid * 4] = make_float4(e0 * inv, e1 * inv, e2 * inv, e3 * inv);
        }
    } else if (bid == N_) {
        int j = t >> 3, l = t & 7;
        float p = 0.f;
        for (int u = l; u < U_; u += 8) p += na[u] * W1[u * 32 + j];
        red[t] = p;
        __syncthreads();
        if (l == 0) {
            float s = 0.f;
            for (int q = 0; q < 8; q++) s += red[j * 8 + q];
            h32[j] = fmaxf(s + b1[j], 0.f);
        }
        __syncthreads();
        for (int u = t; u < U_; u += 256) {
            float s = b2[u];
            #pragma unroll
            for (int jj = 0; jj < 32; jj++) s += h32[jj] * W2[jj * U_ + u];
            g_cm[u] = mask[u] * sigmoidf_(s);
        }
    } else if (bid == N_ + 1) {
        if (t == 0) {
            float m = -1e30f;
            for (int i = 0; i < 9; i++) m = fmaxf(m, aw[i]);
            float e[9], s = 0.f;
            for (int i = 0; i < 9; i++) { e[i] = expf(aw[i] - m); s += e[i]; }
            float inv = 1.f / s;
            for (int i = 0; i < 8; i++) g_wts[i] = e[i] * inv;
        }
    } else {
        int bc = bid - (N_ + 2);
        int rc = bc >> 5, cc = bc & 31;
        int c = cc * 32 + (t & 31), ty = t >> 5;
        float s = 0.f;
        const float* p = mem + (size_t)(rc * 1024 + ty) * MD_ + c;
        #pragma unroll 4
        for (int i = 0; i < 128; i++) s += p[(size_t)i * 8 * MD_];
        red[t] = s;
        __syncthreads();
        if (ty == 0) {
            float tot = 0.f;
            #pragma unroll
            for (int q = 0; q < 8; q++) tot += red[q * 32 + (t & 31)];
            g_cmpart[rc * MD_ + c] = tot;
        }
    }
}

// ---------------- elementwise fp32 -> bf16 ----------------
__global__ void k_cvt(const float4* __restrict__ src, __nv_bfloat162* __restrict__ dst) {
    int i = blockIdx.x * blockDim.x + threadIdx.x;
    float4 v = src[i];
    dst[i * 2 + 0] = __floats2bfloat162_rn(v.x, v.y);
    dst[i * 2 + 1] = __floats2bfloat162_rn(v.z, v.w);
}

// ---------------- w * sigmoid(delay) -> bf16 (elementwise, no transpose) ----------------
__global__ void k_wmod(const float4* __restrict__ w, const float4* __restrict__ delay) {
    int i = blockIdx.x * blockDim.x + threadIdx.x;   // 2M float4s
    float4 wv = w[i], dv = delay[i];
    __nv_bfloat162* o = (__nv_bfloat162*)g_wcb;
    o[i * 2 + 0] = __floats2bfloat162_rn(wv.x * sigmoidf_(dv.x), wv.y * sigmoidf_(dv.y));
    o[i * 2 + 1] = __floats2bfloat162_rn(wv.z * sigmoidf_(dv.z), wv.w * sigmoidf_(dv.w));
}

// ---------------- activation blend (a >= 0) ----------------
__device__ __forceinline__ float blendf(float a, const float* w) {
    const float SELU_SCALE = 1.0507009873554804934f;
    float e = __expf(-a);
    float sig = __fdividef(1.f, 1.f + e);
    float th = tanh_ap(a);
    float gelu = 0.5f * a * (1.f + erff(a * 0.70710678118654752440f));
    float sp = a + __logf(1.f + e);
    float mish = a * tanh_ap(sp);
    return w[0] * sig + w[2] * th + (w[1] + w[3] + SELU_SCALE * w[6]) * a
         + w[4] * a * sig + w[5] * gelu + w[7] * mish;
}

// ---------------- bf16 mma GEMM ----------------
// A [2048,K] bf16 row-major; B [K,NG] bf16 row-major (natural layout, ldmatrix.trans).
// CTA tile (WM*64) x 128, WM*2 warps, warp tile 64x64, BK=32, 4-stage cp.async.
// A smem: 64B rows, chunk swizzle j^=(row>>1)&3. B smem: 32 rows x 256B, chunk c^=(row&7).
template<int K, int NG, int EPI, int WM>
__global__ void __launch_bounds__(WM * 64, 2)
gemm_bf16(const __nv_bfloat16* __restrict__ Ag, const __nv_bfloat16* __restrict__ Bg,
          const float* __restrict__ bias, float* __restrict__ outp) {
    constexpr int NTH    = WM * 64;
    constexpr int ABYTES = WM * 64 * 64;       // WM*64 rows x 64B
    constexpr int STAGE  = ABYTES + 8192;
    constexpr int NBCP   = 512 / NTH;
    constexpr int NC     = K / 32;

    extern __shared__ char smem[];
    const uint32_t sb = smem_u32(smem);
    const int tid = threadIdx.x;
    const int lane = tid & 31, wid = tid >> 5;
    const int wm = wid & (WM - 1), wn = wid >> (WM - 1 ? 1 : 0);
    const int lrow = lane >> 2, lcol = lane & 3;
    const int m0 = blockIdx.y * (WM * 64), n0 = blockIdx.x * 128;

    float acc[4][8][4];
    #pragma unroll
    for (int i = 0; i < 4; i++)
        #pragma unroll
        for (int j = 0; j < 8; j++)
            #pragma unroll
            for (int q = 0; q < 4; q++) acc[i][j][q] = 0.f;

    // cp.async loop-invariant offsets
    const char* baseA = (const char*)(Ag + (size_t)m0 * K);
    const char* baseB = (const char*)(Bg + n0);
    uint32_t ago[4], asmo[4], bgo[NBCP], bsmo[NBCP];
    #pragma unroll
    for (int i = 0; i < 4; i++) {
        int id = tid + i * NTH, r = id >> 2, j = id & 3;
        ago[i] = r * (K * 2) + j * 16;
        asmo[i] = r * 64 + ((j ^ ((r >> 1) & 3)) << 4);
    }
    #pragma unroll
    for (int i = 0; i < NBCP; i++) {
        int id = tid + i * NTH, r = id >> 4, c = id & 15;
        bgo[i] = r * (NG * 2) + c * 16;
        bsmo[i] = r * 256 + ((c ^ (r & 7)) << 4);
    }

    // ldmatrix loop-invariant offsets
    const int msel = lane >> 3;
    uint32_t aoff[4], boff[4];
    #pragma unroll
    for (int i = 0; i < 4; i++) {
        int row = wm * 64 + i * 16 + (msel & 1) * 8 + (lane & 7);
        int kc = msel >> 1;
        aoff[i] = row * 64 + ((kc ^ ((row >> 1) & 3)) << 4);
    }
    #pragma unroll
    for (int jg = 0; jg < 4; jg++) {
        int krow = (msel & 1) * 8 + (lane & 7);
        int c = wn * 8 + jg * 2 + (msel >> 1);
        boff[jg] = krow * 256 + ((c ^ (krow & 7)) << 4);
    }

    auto load_stage = [&](int sidx) {
        uint32_t sA = sb + sidx * STAGE, sB = sA + ABYTES;
        #pragma unroll
        for (int i = 0; i < 4; i++) cp16(sA + asmo[i], baseA + ago[i]);
        #pragma unroll
        for (int i = 0; i < NBCP; i++) cp16(sB + bsmo[i], baseB + bgo[i]);
        cp_commit();
        baseA += 64;
        baseB += (size_t)32 * NG * 2;
    };
    load_stage(0);
    load_stage(1);
    load_stage(2);

    #pragma unroll 1
    for (int c = 0; c < NC; c++) {
        // wait until stage c is complete: allowed pending = min(c+3, NC) - (c+1)
        if (c + 2 < NC)      cp_wait<2>();
        else if (c + 1 < NC) cp_wait<1>();
        else                 cp_wait<0>();
        __syncthreads();
        if (c + 3 < NC) load_stage((c + 3) & 3);
        uint32_t sA = sb + (c & 3) * STAGE, sB = sA + ABYTES;

        #pragma unroll
        for (int s = 0; s < 2; s++) {
            uint32_t av[4][4], bv[8][2];
            #pragma unroll
            for (int i = 0; i < 4; i++)
                ldsm4(av[i][0], av[i][1], av[i][2], av[i][3],
                      sA + (s ? (aoff[i] ^ 0x20u) : aoff[i]));
            #pragma unroll
            for (int jg = 0; jg < 4; jg++) {
                uint32_t r0, r1, r2, r3;
                ldsm4t(r0, r1, r2, r3, sB + boff[jg] + s * 4096);
                bv[2 * jg][0] = r0;     bv[2 * jg][1] = r1;
                bv[2 * jg + 1][0] = r2; bv[2 * jg + 1][1] = r3;
            }
            #pragma unroll
            for (int i = 0; i < 4; i++)
                #pragma unroll
                for (int j = 0; j < 8; j++)
                    mma_bf16(acc[i][j], av[i], bv[j]);
        }
    }

    // ---------------- epilogues ----------------
    if (EPI == 0) {
        float w[8];
        #pragma unroll
        for (int q = 0; q < 8; q++) w[q] = g_wts[q];
        const int cb = (lane & 1) * 2;
        #pragma unroll
        for (int i = 0; i < 4; i++) {
            int r0 = m0 + wm * 64 + i * 16 + lrow;
            int r1 = r0 + 8;
            float gA0 = g_gate[r0 * 4 + cb], gA1 = g_gate[r0 * 4 + cb + 1];
            float gB0 = g_gate[r1 * 4 + cb], gB1 = g_gate[r1 * 4 + cb + 1];
            #pragma unroll
            for (int j = 0; j < 8; j++) {
                int col0 = n0 + wn * 64 + j * 8 + 2 * lcol;
                float bb0 = bias[col0], bb1 = bias[col0 + 1];
                float pl = (acc[i][j][0] + bb0) * gA0 + (acc[i][j][1] + bb1) * gA1;
                float ph = (acc[i][j][2] + bb0) * gB0 + (acc[i][j][3] + bb1) * gB1;
                pl += __shfl_xor_sync(0xFFFFFFFFu, pl, 1);
                ph += __shfl_xor_sync(0xFFFFFFFFu, ph, 1);
                float z = (lane & 1) ? ph : pl;
                int row = (lane & 1) ? r1 : r0;
                int u = (n0 + wn * 64 + j * 8 + (lane & 2) * 2) >> 2;
                float a = fmaxf(z * g_cm[u], 0.f);
                g_blend[(size_t)row * U_ + u] = __float2bfloat16(blendf(a, w));
            }
        }
    } else if (EPI == 1) {
        #pragma unroll
        for (int i = 0; i < 4; i++) {
            int r0 = m0 + wm * 64 + i * 16 + lrow;
            int r1 = r0 + 8;
            #pragma unroll
            for (int j = 0; j < 8; j++) {
                int col0 = n0 + wn * 64 + j * 8 + 2 * lcol;
                float bb0 = bias[col0], bb1 = bias[col0 + 1];
                *(float2*)&g_logits[(size_t)r0 * M_ + col0] =
                    make_float2(acc[i][j][0] + bb0, acc[i][j][1] + bb1);
                *(float2*)&g_logits[(size_t)r1 * M_ + col0] =
                    make_float2(acc[i][j][2] + bb0, acc[i][j][3] + bb1);
            }
        }
    } else {
        __syncthreads();
        float* cms = (float*)smem;
        for (int tq = tid; tq < 128; tq += NTH) {
            float s = 0.f;
            #pragma unroll
            for (int p = 0; p < 8; p++) s += g_cmpart[p * MD_ + n0 + tq];
            cms[tq] = s * (1.f / (float)M_);
        }
        __syncthreads();
        #pragma unroll
        for (int i = 0; i < 4; i++) {
            int r0 = m0 + wm * 64 + i * 16 + lrow;
            int r1 = r0 + 8;
            #pragma unroll
            for (int j = 0; j < 8; j++) {
                int col0 = n0 + wn * 64 + j * 8 + 2 * lcol;
                float cm0 = cms[col0 - n0], cm1 = cms[col0 + 1 - n0];
                *(float2*)&outp[(size_t)r0 * MD_ + col0] =
                    make_float2(acc[i][j][0] + cm0, acc[i][j][1] + cm1);
                *(float2*)&outp[(size_t)r1 * MD_ + col0] =
                    make_float2(acc[i][j][2] + cm0, acc[i][j][3] + cm1);
            }
        }
    }
}

// ---------------- softmax: fp32 logits -> bf16 (attn - 1/M) ----------------
__global__ void __launch_bounds__(256) k_softmax() {
    __shared__ float sm[256];
    int n = blockIdx.x, t = threadIdx.x;
    const float4* row4 = (const float4*)&g_logits[(size_t)n * M_];
    float4 v[8];
    float mx = -3.4e38f;
    #pragma unroll
    for (int i = 0; i < 8; i++) {
        v[i] = row4[t + i * 256];
        mx = fmaxf(mx, fmaxf(fmaxf(v[i].x, v[i].y), fmaxf(v[i].z, v[i].w)));
    }
    sm[t] = mx; __syncthreads();
    for (int o = 128; o > 0; o >>= 1) {
        if (t < o) sm[t] = fmaxf(sm[t], sm[t + o]);
        __syncthreads();
    }
    mx = sm[0]; __syncthreads();
    float s = 0.f;
    #pragma unroll
    for (int i = 0; i < 8; i++) {
        v[i].x = expf(v[i].x - mx); v[i].y = expf(v[i].y - mx);
        v[i].z = expf(v[i].z - mx); v[i].w = expf(v[i].w - mx);
        s += v[i].x + v[i].y + v[i].z + v[i].w;
    }
    sm[t] = s; __syncthreads();
    for (int o = 128; o > 0; o >>= 1) {
        if (t < o) sm[t] += sm[t + o];
        __syncthreads();
    }
    float inv = 1.f / sm[0];
    const float im = 1.f / (float)M_;
    uint2* dst = (uint2*)&g_attnd[(size_t)n * M_];
    #pragma unroll
    for (int i = 0; i < 8; i++) {
        uint2 o;
        __nv_bfloat162* h = (__nv_bfloat162*)&o;
        h[0] = __floats2bfloat162_rn(v[i].x * inv - im, v[i].y * inv - im);
        h[1] = __floats2bfloat162_rn(v[i].z * inv - im, v[i].w * inv - im);
        dst[t + i * 256] = o;
    }
}

// ---------------- launch ----------------
extern "C" void kernel_launch(void* const* d_in, const int* in_sizes, int n_in,
                              void* d_out, int out_size) {
    const float* x        = (const float*)d_in[0];
    const float* w        = (const float*)d_in[1];
    const float* delay    = (const float*)d_in[2];
    const float* b        = (const float*)d_in[3];
    const float* gate_W   = (const float*)d_in[4];
    const float* gate_b   = (const float*)d_in[5];
    const float* navg     = (const float*)d_in[6];
    const float* conn_W1  = (const float*)d_in[7];
    const float* conn_b1  = (const float*)d_in[8];
    const float* conn_W2  = (const float*)d_in[9];
    const float* conn_b2  = (const float*)d_in[10];
    const float* mask     = (const float*)d_in[11];
    const float* act_w    = (const float*)d_in[12];
    const float* read_W   = (const float*)d_in[13];
    const float* read_b   = (const float*)d_in[14];
    const float* memory   = (const float*)d_in[15];
    float* out = (float*)d_out;

    __nv_bfloat16 *p_xbf, *p_wcb, *p_rwb, *p_memb, *p_blend, *p_attnd;
    cudaGetSymbolAddress((void**)&p_xbf, g_xbf);
    cudaGetSymbolAddress((void**)&p_wcb, g_wcb);
    cudaGetSymbolAddress((void**)&p_rwb, g_rwb);
    cudaGetSymbolAddress((void**)&p_memb, g_memb);
    cudaGetSymbolAddress((void**)&p_blend, g_blend);
    cudaGetSymbolAddress((void**)&p_attnd, g_attnd);

    cudaFuncSetAttribute(gemm_bf16<D_, U_ * NB_, 0, 2>,
                         cudaFuncAttributeMaxDynamicSharedMemorySize, 65536);
    cudaFuncSetAttribute(gemm_bf16<U_, M_, 1, 2>,
                         cudaFuncAttributeMaxDynamicSharedMemorySize, 65536);
    cudaFuncSetAttribute(gemm_bf16<M_, MD_, 2, 1>,
                         cudaFuncAttributeMaxDynamicSharedMemorySize, 49152);

    // 1: misc (gate/conn/actw/colsums)
    k_misc<<<N_ + 2 + 256, 256>>>(x, gate_W, gate_b, navg, conn_W1, conn_b1,
                                  conn_W2, conn_b2, mask, act_w, memory);
    // 2: x -> bf16
    k_cvt<<<2048, 256>>>((const float4*)x, (__nv_bfloat162*)p_xbf);
    // 3: w * sigmoid(delay) -> bf16 (natural layout)
    k_wmod<<<8192, 256>>>((const float4*)w, (const float4*)delay);
    // 4: GEMM1 (profiled slot)
    gemm_bf16<D_, U_ * NB_, 0, 2><<<dim3(64, 16), 128, 65536>>>(p_xbf, p_wcb, b, nullptr);
    // 5: read_W -> bf16
    k_cvt<<<16384, 256>>>((const float4*)read_W, (__nv_bfloat162*)p_rwb);
    // 6: GEMM2 -> logits (fp32)
    gemm_bf16<U_, M_, 1, 2><<<dim3(64, 16), 128, 65536>>>(p_blend, p_rwb, read_b, nullptr);
    // 7: softmax -> attnd (bf16)
    k_softmax<<<N_, 256>>>();
    // 8: memory -> bf16
    k_cvt<<<8192, 256>>>((const float4*)memory, (__nv_bfloat162*)p_memb);
    // 9: GEMM3 -> out (+ colmean)
    gemm_bf16<M_, MD_, 2, 1><<<dim3(8, 32), 64, 49152>>>(p_attnd, p_memb, nullptr, out);
}